// round 3
// baseline (speedup 1.0000x reference)
#include <cuda_runtime.h>
#include <math.h>

// Problem constants
#define NS 256          // N sequences
#define LR 384          // L residues
#define DM 256          // D_MSA
#define DP 128          // D_PAIR
#define NH 8            // heads
#define DHH 32          // head dim
#define HDM 256         // H*DH
#define NL (NS*LR)      // 98304
#define LL (LR*LR)      // 147456

#define SCALE_DH 0.17677669529663687f  // 1/sqrt(32)

// ---------------- scratch (device globals; no runtime alloc allowed) ----------------
__device__ float g_msan[NL*DM];           // LN(msa), row-major [n*L+l][D]
__device__ float g_swq[LR*HDM];           // (tar@sw_q_w + b)*scale, [l][hd]
__device__ float g_swk[NL*HDM];           // msa_n@sw_k_w + b, [r][hd]
__device__ float g_q[NH*LR*NS*DHH];       // [h][l][n][d]  (raw, later *= seq_weight)
__device__ float g_k[NH*LR*NS*DHH];       // [h][l][n][d]  (includes *scale)
__device__ float g_v[NS*NH*LR*DHH];       // [s][h][k][d]
__device__ float g_gate[NL*HDM];          // sigmoid(msa_n@wg + bg), [r][hd]
__device__ float g_logit[LR*NH*NS];       // sw logits, [l][h][n]
__device__ float g_bias[NH*LL];           // LN(pair)@wb, [h][q][k]
__device__ float g_attn[NH*LL];           // attention logits -> probs, [h][q][k]
__device__ float g_out[NL*HDM];           // attention output (pre-gate), [s*L+q][hd]

// ---------------- warp reduce helpers ----------------
__device__ __forceinline__ float warpRed(float v){
    #pragma unroll
    for(int o=16;o>0;o>>=1) v += __shfl_xor_sync(0xffffffffu, v, o);
    return v;
}
__device__ __forceinline__ float warpMax(float v){
    #pragma unroll
    for(int o=16;o>0;o>>=1) v = fmaxf(v, __shfl_xor_sync(0xffffffffu, v, o));
    return v;
}

// ---------------- 1. LayerNorm of msa ----------------
__global__ void ln_msa_kernel(const float* __restrict__ x,
                              const float* __restrict__ gg,
                              const float* __restrict__ bb){
    __shared__ float s1[8], s2[8];
    int row = blockIdx.x, tid = threadIdx.x;
    float v = x[row*DM + tid];
    float a = warpRed(v);
    float b = warpRed(v*v);
    if((tid&31)==0){ s1[tid>>5]=a; s2[tid>>5]=b; }
    __syncthreads();
    if(tid<32){
        float aa = (tid<8)? s1[tid] : 0.f;
        float bb2 = (tid<8)? s2[tid] : 0.f;
        aa = warpRed(aa); bb2 = warpRed(bb2);
        if(tid==0){ s1[0]=aa; s2[0]=bb2; }
    }
    __syncthreads();
    float mean = s1[0]*(1.f/DM);
    float var  = s2[0]*(1.f/DM) - mean*mean;
    float inv  = rsqrtf(var + 1e-5f);
    g_msan[row*DM + tid] = (v-mean)*inv*gg[tid] + bb[tid];
}

// ---------------- 2. swq = (msa_n[n=0] @ sw_q_w + b) * scale ----------------
__global__ void swq_kernel(const float* __restrict__ W, const float* __restrict__ bqb){
    __shared__ float t[DM];
    int l = blockIdx.x, tid = threadIdx.x;
    t[tid] = g_msan[l*DM + tid];   // n=0 row is r = l
    __syncthreads();
    float acc = 0.f;
    #pragma unroll 8
    for(int k=0;k<DM;k++) acc += t[k]*W[k*HDM + tid];
    g_swq[l*HDM + tid] = (acc + bqb[tid]) * SCALE_DH;
}

// ---------------- 3. fused projections GEMM [NL x 256] @ [256 x 5*256] ----------------
// BM=BN=64, BK=32, 256 threads, 4x4 register tile. Epilogue scatters into
// attention-friendly layouts per target matrix.
__global__ void proj_kernel(const float* __restrict__ wq, const float* __restrict__ wk,
                            const float* __restrict__ wv, const float* __restrict__ wg,
                            const float* __restrict__ wsk, const float* __restrict__ bg,
                            const float* __restrict__ skb){
    const int mat = blockIdx.x >> 2;            // 0..4
    const int c0  = (blockIdx.x & 3) * 64;      // col offset within its matrix
    const int r0  = blockIdx.y * 64;
    const float* W = (mat==0)?wq:(mat==1)?wk:(mat==2)?wv:(mat==3)?wg:wsk;

    __shared__ float As[64][33];
    __shared__ float Ws[32][64];

    const int tid = threadIdx.x;
    const int tx = tid & 15, ty = tid >> 4;
    float acc[4][4] = {};

    for(int k0=0;k0<DM;k0+=32){
        #pragma unroll
        for(int t=0;t<2;t++){
            int fi = tid*2+t;          // 0..511
            int row = fi >> 3, cf = fi & 7;
            float4 a4 = *(const float4*)&g_msan[(r0+row)*DM + k0 + cf*4];
            As[row][cf*4+0]=a4.x; As[row][cf*4+1]=a4.y;
            As[row][cf*4+2]=a4.z; As[row][cf*4+3]=a4.w;
        }
        #pragma unroll
        for(int t=0;t<2;t++){
            int fi = tid*2+t;
            int row = fi >> 4, cf = fi & 15;
            *(float4*)&Ws[row][cf*4] = *(const float4*)&W[(k0+row)*HDM + c0 + cf*4];
        }
        __syncthreads();
        #pragma unroll
        for(int kk=0;kk<32;kk++){
            float a[4], b[4];
            #pragma unroll
            for(int i=0;i<4;i++) a[i] = As[ty*4+i][kk];
            float4 b4 = *(const float4*)&Ws[kk][tx*4];
            b[0]=b4.x; b[1]=b4.y; b[2]=b4.z; b[3]=b4.w;
            #pragma unroll
            for(int i=0;i<4;i++)
                #pragma unroll
                for(int j=0;j<4;j++) acc[i][j] += a[i]*b[j];
        }
        __syncthreads();
    }

    #pragma unroll
    for(int i=0;i<4;i++){
        int r = r0 + ty*4 + i;
        int n = r / LR, l = r % LR;
        #pragma unroll
        for(int j=0;j<4;j++){
            int c = c0 + tx*4 + j;
            float v = acc[i][j];
            int h = c >> 5, d = c & 31;
            if(mat==0)      g_q[((h*LR+l)*NS+n)*DHH + d] = v;
            else if(mat==1) g_k[((h*LR+l)*NS+n)*DHH + d] = v * SCALE_DH;
            else if(mat==2) g_v[((n*NH+h)*LR+l)*DHH + d] = v;
            else if(mat==3) g_gate[r*HDM + c] = 1.f/(1.f + expf(-(v + bg[c])));
            else            g_swk[r*HDM + c] = v + skb[c];
        }
    }
}

// ---------------- 4. sw logits: per (n,l,h) dot32(swq, swk) ----------------
__global__ void logit_kernel(){
    int warp = threadIdx.x >> 5, lane = threadIdx.x & 31;
    int r = blockIdx.x*8 + warp;           // r = n*L + l
    int n = r / LR, l = r % LR;
    const float* swkrow = g_swk + r*HDM;
    const float* swqrow = g_swq + l*HDM;
    #pragma unroll
    for(int h=0;h<NH;h++){
        float p = swqrow[h*32+lane]*swkrow[h*32+lane];
        p = warpRed(p);
        if(lane==0) g_logit[(l*NH+h)*NS + n] = p;
    }
}

// ---------------- 5. softmax over n + scale q in place ----------------
__global__ void seq_softmax_kernel(){
    __shared__ float sh[8];
    __shared__ float wsh[NS];
    int l = blockIdx.x >> 3, h = blockIdx.x & 7;
    int tid = threadIdx.x;                 // = n
    float x = g_logit[(l*NH+h)*NS + tid];
    float m = warpMax(x);
    if((tid&31)==0) sh[tid>>5]=m;
    __syncthreads();
    if(tid<32){ float mm=(tid<8)?sh[tid]:-1e30f; mm=warpMax(mm); if(tid==0) sh[0]=mm; }
    __syncthreads();
    m = sh[0];
    __syncthreads();
    float e = expf(x - m);
    float s = warpRed(e);
    if((tid&31)==0) sh[tid>>5]=s;
    __syncthreads();
    if(tid<32){ float ss=(tid<8)?sh[tid]:0.f; ss=warpRed(ss); if(tid==0) sh[0]=ss; }
    __syncthreads();
    s = sh[0];
    wsh[tid] = e / s;
    __syncthreads();
    float* qb = g_q + (h*LR + l)*NS*DHH;
    for(int idx=tid; idx<NS*DHH; idx+=256) qb[idx] *= wsh[idx>>5];
}

// ---------------- 6. bias = LN(pair) @ wb, fused ----------------
__global__ void bias_kernel(const float* __restrict__ pair, const float* __restrict__ g,
                            const float* __restrict__ b, const float* __restrict__ wb){
    __shared__ float wbs[NH][DP];     // transposed for float4 reads
    int tid = threadIdx.x;
    for(int idx=tid; idx<NH*DP; idx+=256){
        int h = idx / DP, k = idx % DP;
        wbs[h][k] = wb[k*NH + h];
    }
    __syncthreads();
    int warp = tid >> 5, lane = tid & 31;
    int p = blockIdx.x*8 + warp;        // p = i*L + j
    float4 xv = ((const float4*)(pair + p*DP))[lane];
    float sum = xv.x+xv.y+xv.z+xv.w;
    float sq  = xv.x*xv.x+xv.y*xv.y+xv.z*xv.z+xv.w*xv.w;
    sum = warpRed(sum); sq = warpRed(sq);
    float mean = sum*(1.f/DP);
    float var  = sq*(1.f/DP) - mean*mean;
    float inv  = rsqrtf(var + 1e-5f);
    float4 gv = ((const float4*)g)[lane];
    float4 bv = ((const float4*)b)[lane];
    float xn0 = (xv.x-mean)*inv*gv.x + bv.x;
    float xn1 = (xv.y-mean)*inv*gv.y + bv.y;
    float xn2 = (xv.z-mean)*inv*gv.z + bv.z;
    float xn3 = (xv.w-mean)*inv*gv.w + bv.w;
    #pragma unroll
    for(int h=0;h<NH;h++){
        float4 wv4 = ((const float4*)(wbs[h]))[lane];
        float prt = xn0*wv4.x + xn1*wv4.y + xn2*wv4.z + xn3*wv4.w;
        prt = warpRed(prt);
        if(lane==0) g_bias[h*LL + p] = prt;
    }
}

// ---------------- 7. QK: per head, C[q,k] = sum_{sd} Qw * K ----------------
__global__ void qk_kernel(){
    const int h = blockIdx.z;
    const int q0 = blockIdx.y*64, k0c = blockIdx.x*64;
    const float* A = g_q + h*LR*NS*DHH;   // [LR][8192]
    const float* B = g_k + h*LR*NS*DHH;
    __shared__ float As[64][33];
    __shared__ float Bs[64][33];
    const int tid = threadIdx.x;
    const int tx = tid & 15, ty = tid >> 4;
    float acc[4][4] = {};
    const int KD = NS*DHH;  // 8192
    for(int m0=0;m0<KD;m0+=32){
        #pragma unroll
        for(int t=0;t<2;t++){
            int fi = tid*2+t;
            int row = fi >> 3, cf = fi & 7;
            float4 a4 = *(const float4*)&A[(q0+row)*KD + m0 + cf*4];
            As[row][cf*4+0]=a4.x; As[row][cf*4+1]=a4.y;
            As[row][cf*4+2]=a4.z; As[row][cf*4+3]=a4.w;
            float4 b4 = *(const float4*)&B[(k0c+row)*KD + m0 + cf*4];
            Bs[row][cf*4+0]=b4.x; Bs[row][cf*4+1]=b4.y;
            Bs[row][cf*4+2]=b4.z; Bs[row][cf*4+3]=b4.w;
        }
        __syncthreads();
        #pragma unroll
        for(int kk=0;kk<32;kk++){
            float a[4], b[4];
            #pragma unroll
            for(int i=0;i<4;i++) a[i] = As[ty*4+i][kk];
            #pragma unroll
            for(int j=0;j<4;j++) b[j] = Bs[tx*4+j][kk];
            #pragma unroll
            for(int i=0;i<4;i++)
                #pragma unroll
                for(int j=0;j<4;j++) acc[i][j] += a[i]*b[j];
        }
        __syncthreads();
    }
    #pragma unroll
    for(int i=0;i<4;i++)
        #pragma unroll
        for(int j=0;j<4;j++)
            g_attn[h*LL + (q0+ty*4+i)*LR + (k0c+tx*4+j)] = acc[i][j];
}

// ---------------- 8. softmax over k (+ bias) per (h,q) row ----------------
__global__ void attn_softmax_kernel(){
    __shared__ float sh[4];
    int row = blockIdx.x;   // h*LR + q
    float* a = g_attn + row*LR;
    const float* bi = g_bias + row*LR;
    int tid = threadIdx.x;  // 128 threads
    float x0 = a[tid]       + bi[tid];
    float x1 = a[tid+128]   + bi[tid+128];
    float x2 = a[tid+256]   + bi[tid+256];
    float m = fmaxf(x0, fmaxf(x1, x2));
    m = warpMax(m);
    if((tid&31)==0) sh[tid>>5]=m;
    __syncthreads();
    if(tid<32){ float mm=(tid<4)?sh[tid]:-1e30f; mm=warpMax(mm); if(tid==0) sh[0]=mm; }
    __syncthreads();
    m = sh[0];
    __syncthreads();
    x0 = expf(x0-m); x1 = expf(x1-m); x2 = expf(x2-m);
    float s = warpRed(x0+x1+x2);
    if((tid&31)==0) sh[tid>>5]=s;
    __syncthreads();
    if(tid<32){ float ss=(tid<4)?sh[tid]:0.f; ss=warpRed(ss); if(tid==0) sh[0]=ss; }
    __syncthreads();
    s = sh[0];
    float r = 1.f/s;
    a[tid]=x0*r; a[tid+128]=x1*r; a[tid+256]=x2*r;
}

// ---------------- 9. AV: per (s,h): out[q,d] = P[q,:] @ V[:,d] ----------------
__global__ void av_kernel(){
    const int q0 = blockIdx.x*64;
    const int h  = blockIdx.y;
    const int s  = blockIdx.z;
    __shared__ float Ps[64][65];
    __shared__ float Vs[64][32];
    const int tid = threadIdx.x;
    const int tx = tid & 31, ty = tid >> 5;   // tx=d, ty in 0..7
    const float* P = g_attn + (h*LR + q0)*LR;
    const float* V = g_v + (s*NH + h)*LR*DHH;
    float acc[8] = {};
    for(int k0=0;k0<LR;k0+=64){
        for(int idx=tid; idx<64*64; idx+=256){
            int qq = idx >> 6, kk = idx & 63;
            Ps[qq][kk] = P[qq*LR + k0 + kk];
        }
        for(int idx=tid; idx<64*32; idx+=256){
            int kk = idx >> 5, dd = idx & 31;
            Vs[kk][dd] = V[(k0+kk)*DHH + dd];
        }
        __syncthreads();
        #pragma unroll
        for(int kk=0;kk<64;kk++){
            float vv = Vs[kk][tx];
            #pragma unroll
            for(int i=0;i<8;i++) acc[i] += Ps[i*8+ty][kk]*vv;
        }
        __syncthreads();
    }
    #pragma unroll
    for(int i=0;i<8;i++){
        int q = q0 + i*8 + ty;
        g_out[(s*LR + q)*HDM + h*DHH + tx] = acc[i];
    }
}

// ---------------- 10. final: out = (gate * g_out) @ wo + bo ----------------
__global__ void out_kernel(const float* __restrict__ wo, const float* __restrict__ bo,
                           float* __restrict__ out){
    const int c0 = blockIdx.x*64, r0 = blockIdx.y*64;
    __shared__ float As[64][33];
    __shared__ float Ws[32][64];
    const int tid = threadIdx.x;
    const int tx = tid & 15, ty = tid >> 4;
    float acc[4][4] = {};
    for(int k0=0;k0<HDM;k0+=32){
        #pragma unroll
        for(int t=0;t<2;t++){
            int fi = tid*2+t;
            int row = fi >> 3, cf = fi & 7;
            float4 a4 = *(const float4*)&g_out[(r0+row)*HDM + k0 + cf*4];
            float4 gv = *(const float4*)&g_gate[(r0+row)*HDM + k0 + cf*4];
            As[row][cf*4+0]=a4.x*gv.x; As[row][cf*4+1]=a4.y*gv.y;
            As[row][cf*4+2]=a4.z*gv.z; As[row][cf*4+3]=a4.w*gv.w;
        }
        #pragma unroll
        for(int t=0;t<2;t++){
            int fi = tid*2+t;
            int row = fi >> 4, cf = fi & 15;
            *(float4*)&Ws[row][cf*4] = *(const float4*)&wo[(k0+row)*DM + c0 + cf*4];
        }
        __syncthreads();
        #pragma unroll
        for(int kk=0;kk<32;kk++){
            float a[4], b[4];
            #pragma unroll
            for(int i=0;i<4;i++) a[i] = As[ty*4+i][kk];
            float4 b4 = *(const float4*)&Ws[kk][tx*4];
            b[0]=b4.x; b[1]=b4.y; b[2]=b4.z; b[3]=b4.w;
            #pragma unroll
            for(int i=0;i<4;i++)
                #pragma unroll
                for(int j=0;j<4;j++) acc[i][j] += a[i]*b[j];
        }
        __syncthreads();
    }
    #pragma unroll
    for(int i=0;i<4;i++){
        int r = r0 + ty*4 + i;
        #pragma unroll
        for(int j=0;j<4;j++){
            int c = c0 + tx*4 + j;
            out[r*DM + c] = acc[i][j] + bo[c];
        }
    }
}

// ---------------- launch ----------------
extern "C" void kernel_launch(void* const* d_in, const int* in_sizes, int n_in,
                              void* d_out, int out_size){
    const float* msa       = (const float*)d_in[0];
    const float* pair      = (const float*)d_in[1];
    const float* ln_msa_g  = (const float*)d_in[2];
    const float* ln_msa_b  = (const float*)d_in[3];
    const float* ln_pair_g = (const float*)d_in[4];
    const float* ln_pair_b = (const float*)d_in[5];
    const float* sw_q_w    = (const float*)d_in[6];
    const float* sw_q_b    = (const float*)d_in[7];
    const float* sw_k_w    = (const float*)d_in[8];
    const float* sw_k_b    = (const float*)d_in[9];
    const float* wq        = (const float*)d_in[10];
    const float* wk        = (const float*)d_in[11];
    const float* wv        = (const float*)d_in[12];
    const float* wb        = (const float*)d_in[13];
    const float* wg        = (const float*)d_in[14];
    const float* bg        = (const float*)d_in[15];
    const float* wo        = (const float*)d_in[16];
    const float* bo        = (const float*)d_in[17];
    float* out = (float*)d_out;

    ln_msa_kernel<<<NL, 256>>>(msa, ln_msa_g, ln_msa_b);
    swq_kernel<<<LR, 256>>>(sw_q_w, sw_q_b);
    proj_kernel<<<dim3(20, NL/64), 256>>>(wq, wk, wv, wg, sw_k_w, bg, sw_k_b);
    logit_kernel<<<NL/8, 256>>>();
    seq_softmax_kernel<<<LR*NH, 256>>>();
    bias_kernel<<<LL/8, 256>>>(pair, ln_pair_g, ln_pair_b, wb);
    qk_kernel<<<dim3(LR/64, LR/64, NH), 256>>>();
    attn_softmax_kernel<<<NH*LR, 128>>>();
    av_kernel<<<dim3(LR/64, NH, NS), 256>>>();
    out_kernel<<<dim3(DM/64, NL/64), 256>>>(wo, bo, out);
}

// round 5
// speedup vs baseline: 1.8420x; 1.8420x over previous
#include <cuda_runtime.h>
#include <cuda_bf16.h>
#include <math.h>
#include <stdint.h>

// Problem constants
#define NS 256
#define LR 384
#define DM 256
#define DP 128
#define NH 8
#define DHH 32
#define HDM 256
#define NL (NS*LR)      // 98304
#define LL (LR*LR)      // 147456
#define SCALE_DH 0.17677669529663687f

#define PJ_KP 768       // 3*256
#define QK_KP 24576     // 3*8192
#define AV_KP 1152      // 3*384

// ---------------- device scratch ----------------
__device__ float g_msan[NL*DM];
__device__ float g_swq[LR*HDM];
__device__ float g_swk[NL*HDM];
__device__ float g_q[NH*LR*NS*DHH];       // raw q, [h][l][n][d]
__device__ float g_gate[NL*HDM];
__device__ float g_logit[LR*NH*NS];
__device__ float g_bias[NH*LL];
__device__ float g_attn[NH*LL];           // qk logits (accumulated via atomics)

// packed bf16 operands (A pattern = [hi|hi|lo], B pattern = [hi|lo|hi] along K)
__device__ __nv_bfloat16 a_pk[(size_t)NL*PJ_KP];
__device__ __nv_bfloat16 b_pk[1280*PJ_KP];
__device__ __nv_bfloat16 wo_pk[DM*PJ_KP];
__device__ __nv_bfloat16 q_pk[(size_t)NH*LR*QK_KP];
__device__ __nv_bfloat16 k_pk[(size_t)NH*LR*QK_KP];
__device__ __nv_bfloat16 vt_pk[(size_t)NH*NS*DHH*AV_KP];
__device__ __nv_bfloat16 p_pk[(size_t)NH*LR*AV_KP];

// ---------------- helpers ----------------
__device__ __forceinline__ float warpRed(float v){
    #pragma unroll
    for(int o=16;o>0;o>>=1) v += __shfl_xor_sync(0xffffffffu, v, o);
    return v;
}
__device__ __forceinline__ float warpMax(float v){
    #pragma unroll
    for(int o=16;o>0;o>>=1) v = fmaxf(v, __shfl_xor_sync(0xffffffffu, v, o));
    return v;
}
__device__ __forceinline__ void bsplit(float x, __nv_bfloat16& h, __nv_bfloat16& l){
    h = __float2bfloat16(x);
    l = __float2bfloat16(x - __bfloat162float(h));
}
__device__ __forceinline__ uint32_t s2u(const void* p){
    uint32_t a; asm("{ .reg .u64 t; cvta.to.shared.u64 t, %1; cvt.u32.u64 %0, t; }" : "=r"(a) : "l"(p));
    return a;
}

// ---------------- 1. LayerNorm of msa + pack A ----------------
__global__ void ln_msa_kernel(const float* __restrict__ x,
                              const float* __restrict__ gg,
                              const float* __restrict__ bb){
    __shared__ float s1[8], s2[8];
    int row = blockIdx.x, tid = threadIdx.x;
    float v = x[row*DM + tid];
    float a = warpRed(v);
    float b = warpRed(v*v);
    if((tid&31)==0){ s1[tid>>5]=a; s2[tid>>5]=b; }
    __syncthreads();
    if(tid<32){
        float aa = (tid<8)? s1[tid] : 0.f;
        float bb2 = (tid<8)? s2[tid] : 0.f;
        aa = warpRed(aa); bb2 = warpRed(bb2);
        if(tid==0){ s1[0]=aa; s2[0]=bb2; }
    }
    __syncthreads();
    float mean = s1[0]*(1.f/DM);
    float var  = s2[0]*(1.f/DM) - mean*mean;
    float inv  = rsqrtf(var + 1e-5f);
    float y = (v-mean)*inv*gg[tid] + bb[tid];
    g_msan[row*DM + tid] = y;
    __nv_bfloat16 hi, lo; bsplit(y, hi, lo);
    size_t base = (size_t)row*PJ_KP;
    a_pk[base + tid]       = hi;
    a_pk[base + 256 + tid] = hi;
    a_pk[base + 512 + tid] = lo;
}

// ---------------- 2. pack weights ----------------
__global__ void pack_w_kernel(const float* __restrict__ wq, const float* __restrict__ wk,
                              const float* __restrict__ wv, const float* __restrict__ wg,
                              const float* __restrict__ wsk){
    int n = blockIdx.x, k = threadIdx.x;
    int mat = n >> 8, nl = n & 255;
    const float* W = (mat==0)?wq:(mat==1)?wk:(mat==2)?wv:(mat==3)?wg:wsk;
    float x = W[k*HDM + nl];
    __nv_bfloat16 hi, lo; bsplit(x, hi, lo);
    int base = n*PJ_KP;
    b_pk[base + k]       = hi;
    b_pk[base + 256 + k] = lo;
    b_pk[base + 512 + k] = hi;
}
__global__ void pack_wo_kernel(const float* __restrict__ wo){
    int n = blockIdx.x, k = threadIdx.x;
    float x = wo[k*DM + n];
    __nv_bfloat16 hi, lo; bsplit(x, hi, lo);
    int base = n*PJ_KP;
    wo_pk[base + k]       = hi;
    wo_pk[base + 256 + k] = lo;
    wo_pk[base + 512 + k] = hi;
}

// ---------------- 3. swq ----------------
__global__ void swq_kernel(const float* __restrict__ W, const float* __restrict__ bqb){
    __shared__ float t[DM];
    int l = blockIdx.x, tid = threadIdx.x;
    t[tid] = g_msan[l*DM + tid];
    __syncthreads();
    float acc = 0.f;
    #pragma unroll 8
    for(int k=0;k<DM;k++) acc += t[k]*W[k*HDM + tid];
    g_swq[l*HDM + tid] = (acc + bqb[tid]) * SCALE_DH;
}

// ---------------- zero g_attn (for split-K atomics) ----------------
__global__ void zero_attn_kernel(){
    int i = blockIdx.x*1024 + threadIdx.x;
    if(i < NH*LL) g_attn[i] = 0.f;
}

// ---------------- mma.sync bf16 GEMM ----------------
// C[row,col] = sum_k A[row,k]*B[col,k], both K-major bf16.
// 256 thr / 8 warps. BM=BN=128, BK=32. Warp tile 32x64.
// MODE 0: proj; MODE 1: qk (split-K x4, atomicAdd); MODE 2: av; MODE 3: out.
#define SMPAD 40   // 40 bf16 = 80B row stride (conflict-free for ldmatrix)

template<int MODE>
__device__ __forceinline__ void epi(int R, int Cg, float v, int zz,
        const float* __restrict__ p0, const float* __restrict__ p1,
        float* __restrict__ outp){
    if(MODE==0){
        int n = R/LR, l = R - n*LR;
        int matq = Cg>>8, cl = Cg&255, h = cl>>5, d = cl&31;
        if(matq==0) g_q[((h*LR+l)*NS+n)*DHH + d] = v;
        else if(matq==1){ __nv_bfloat16 hi,lo; bsplit(v*SCALE_DH,hi,lo);
            int bi=(h*LR+l)*QK_KP + n*DHH + d;
            k_pk[bi]=hi; k_pk[bi+8192]=lo; k_pk[bi+16384]=hi; }
        else if(matq==2){ __nv_bfloat16 hi,lo; bsplit(v,hi,lo);
            int bi=(h*NS*DHH+n*DHH+d)*AV_KP + l;
            vt_pk[bi]=hi; vt_pk[bi+LR]=lo; vt_pk[bi+2*LR]=hi; }
        else if(matq==3) g_gate[R*HDM+cl] = 1.f/(1.f+expf(-(v+p0[cl])));
        else g_swk[R*HDM+cl] = v + p1[cl];
    } else if(MODE==1){
        atomicAdd(&g_attn[zz*LL + R*LR + Cg], v);
    } else if(MODE==2){
        int s = Cg>>5, d = Cg&31;
        int rr = s*LR + R;
        float g = g_gate[rr*HDM + zz*DHH + d];
        __nv_bfloat16 hi,lo; bsplit(v*g,hi,lo);
        size_t bi = (size_t)rr*PJ_KP + zz*DHH + d;
        a_pk[bi]=hi; a_pk[bi+256]=hi; a_pk[bi+512]=lo;
    } else {
        outp[R*DM+Cg] = v + p0[Cg];
    }
}

template<int MODE>
__global__ __launch_bounds__(256)
void gemm_mma(const float* __restrict__ p0, const float* __restrict__ p1,
              float* __restrict__ outp){
    constexpr int Kp = (MODE==1) ? QK_KP : (MODE==2) ? AV_KP : PJ_KP;
    __shared__ __nv_bfloat16 As[2][128*SMPAD];
    __shared__ __nv_bfloat16 Bs[2][128*SMPAD];

    const int tid = threadIdx.x, wid = tid>>5, lane = tid&31;
    const int wm = wid & 3, wn = wid >> 2;
    const int nt = blockIdx.x, mt = blockIdx.y, z = blockIdx.z;

    const __nv_bfloat16* A; const __nv_bfloat16* B;
    size_t saz = 0, sbz = 0;
    if(MODE==0){ A = a_pk;  B = b_pk; }
    else if(MODE==1){ A = q_pk; B = k_pk; saz = (size_t)LR*QK_KP; sbz = saz; }
    else if(MODE==2){ A = p_pk; B = vt_pk; saz = (size_t)LR*AV_KP; sbz = (size_t)NS*DHH*AV_KP; }
    else { A = a_pk; B = wo_pk; }

    int zz = z, koff = 0;
    int Cn = Kp/32;
    if(MODE==1){ zz = z>>2; koff = (z&3)*(Kp/4); Cn = Kp/128; }

    const __nv_bfloat16* Ab = A + saz*zz + (size_t)(mt*128)*Kp + koff;
    const __nv_bfloat16* Bb = B + sbz*zz + (size_t)(nt*128)*Kp + koff;

    float acc[2][8][4];
    #pragma unroll
    for(int i=0;i<2;i++)
        #pragma unroll
        for(int j=0;j<8;j++)
            #pragma unroll
            for(int k=0;k<4;k++) acc[i][j][k]=0.f;

    const uint32_t sA0 = s2u(&As[0][0]), sA1 = s2u(&As[1][0]);
    const uint32_t sB0 = s2u(&Bs[0][0]), sB1 = s2u(&Bs[1][0]);

    // --- issue chunk 0 ---
    {
        #pragma unroll
        for(int t=0;t<2;t++){
            int idx = tid + t*256;
            int row = idx>>2, c16 = idx&3;
            uint32_t sa = sA0 + row*(SMPAD*2) + c16*16;
            const void* ga = Ab + (size_t)row*Kp + c16*8;
            asm volatile("cp.async.cg.shared.global [%0], [%1], 16;"::"r"(sa),"l"(ga));
            uint32_t sb = sB0 + row*(SMPAD*2) + c16*16;
            const void* gb = Bb + (size_t)row*Kp + c16*8;
            asm volatile("cp.async.cg.shared.global [%0], [%1], 16;"::"r"(sb),"l"(gb));
        }
        asm volatile("cp.async.commit_group;");
    }

    for(int c = 0; c < Cn; c++){
        const int buf = c & 1;
        if(c+1 < Cn){
            uint32_t sa_b = (buf? sA0 : sA1), sb_b = (buf? sB0 : sB1);
            const __nv_bfloat16* an = Ab + (c+1)*32;
            const __nv_bfloat16* bn = Bb + (c+1)*32;
            #pragma unroll
            for(int t=0;t<2;t++){
                int idx = tid + t*256;
                int row = idx>>2, c16 = idx&3;
                uint32_t sa = sa_b + row*(SMPAD*2) + c16*16;
                const void* ga = an + (size_t)row*Kp + c16*8;
                asm volatile("cp.async.cg.shared.global [%0], [%1], 16;"::"r"(sa),"l"(ga));
                uint32_t sb = sb_b + row*(SMPAD*2) + c16*16;
                const void* gb = bn + (size_t)row*Kp + c16*8;
                asm volatile("cp.async.cg.shared.global [%0], [%1], 16;"::"r"(sb),"l"(gb));
            }
            asm volatile("cp.async.commit_group;");
            asm volatile("cp.async.wait_group 1;");
        } else {
            asm volatile("cp.async.wait_group 0;");
        }
        __syncthreads();

        const uint32_t abase = buf? sA1 : sA0;
        const uint32_t bbase = buf? sB1 : sB0;
        #pragma unroll
        for(int ks=0; ks<2; ks++){
            uint32_t ar[2][4];
            #pragma unroll
            for(int mi=0;mi<2;mi++){
                int row = wm*32 + mi*16 + (lane&15);
                uint32_t addr = abase + row*(SMPAD*2) + ks*32 + (lane>>4)*16;
                asm volatile("ldmatrix.sync.aligned.m8n8.x4.shared.b16 {%0,%1,%2,%3}, [%4];"
                    : "=r"(ar[mi][0]),"=r"(ar[mi][1]),"=r"(ar[mi][2]),"=r"(ar[mi][3])
                    : "r"(addr));
            }
            uint32_t br[4][4];
            #pragma unroll
            for(int nb=0;nb<4;nb++){
                int nrow = wn*64 + nb*16 + (lane&7) + ((lane>>4)&1)*8;
                uint32_t addr = bbase + nrow*(SMPAD*2) + ks*32 + ((lane>>3)&1)*16;
                asm volatile("ldmatrix.sync.aligned.m8n8.x4.shared.b16 {%0,%1,%2,%3}, [%4];"
                    : "=r"(br[nb][0]),"=r"(br[nb][1]),"=r"(br[nb][2]),"=r"(br[nb][3])
                    : "r"(addr));
            }
            #pragma unroll
            for(int mi=0;mi<2;mi++)
                #pragma unroll
                for(int ni=0;ni<8;ni++){
                    uint32_t b0 = br[ni>>1][(ni&1)*2];
                    uint32_t b1 = br[ni>>1][(ni&1)*2+1];
                    float* cc = acc[mi][ni];
                    asm volatile(
                        "mma.sync.aligned.m16n8k16.row.col.f32.bf16.bf16.f32 "
                        "{%0,%1,%2,%3}, {%4,%5,%6,%7}, {%8,%9}, {%0,%1,%2,%3};"
                        : "+f"(cc[0]),"+f"(cc[1]),"+f"(cc[2]),"+f"(cc[3])
                        : "r"(ar[mi][0]),"r"(ar[mi][1]),"r"(ar[mi][2]),"r"(ar[mi][3]),
                          "r"(b0),"r"(b1));
                }
        }
        __syncthreads();
    }

    // epilogue
    const int grow = lane>>2, gcol = (lane&3)*2;
    #pragma unroll
    for(int mi=0;mi<2;mi++){
        #pragma unroll
        for(int ni=0;ni<8;ni++){
            int R0 = mt*128 + wm*32 + mi*16 + grow;
            int C0 = nt*128 + wn*64 + ni*8 + gcol;
            epi<MODE>(R0,   C0,   acc[mi][ni][0], zz, p0, p1, outp);
            epi<MODE>(R0,   C0+1, acc[mi][ni][1], zz, p0, p1, outp);
            epi<MODE>(R0+8, C0,   acc[mi][ni][2], zz, p0, p1, outp);
            epi<MODE>(R0+8, C0+1, acc[mi][ni][3], zz, p0, p1, outp);
        }
    }
}

// ---------------- 4. sw logits ----------------
__global__ void logit_kernel(){
    int warp = threadIdx.x >> 5, lane = threadIdx.x & 31;
    int r = blockIdx.x*8 + warp;
    int n = r / LR, l = r % LR;
    const float* swkrow = g_swk + r*HDM;
    const float* swqrow = g_swq + l*HDM;
    #pragma unroll
    for(int h=0;h<NH;h++){
        float p = swqrow[h*32+lane]*swkrow[h*32+lane];
        p = warpRed(p);
        if(lane==0) g_logit[(l*NH+h)*NS + n] = p;
    }
}

// ---------------- 5. softmax over n + packed weighted q ----------------
__global__ void seq_softmax_kernel(){
    __shared__ float sh[8];
    __shared__ float wsh[NS];
    int l = blockIdx.x >> 3, h = blockIdx.x & 7;
    int tid = threadIdx.x;
    float x = g_logit[(l*NH+h)*NS + tid];
    float m = warpMax(x);
    if((tid&31)==0) sh[tid>>5]=m;
    __syncthreads();
    if(tid<32){ float mm=(tid<8)?sh[tid]:-1e30f; mm=warpMax(mm); if(tid==0) sh[0]=mm; }
    __syncthreads();
    m = sh[0];
    __syncthreads();
    float e = expf(x - m);
    float s = warpRed(e);
    if((tid&31)==0) sh[tid>>5]=s;
    __syncthreads();
    if(tid<32){ float ss=(tid<8)?sh[tid]:0.f; ss=warpRed(ss); if(tid==0) sh[0]=ss; }
    __syncthreads();
    s = sh[0];
    wsh[tid] = e / s;
    __syncthreads();
    const float* qb = g_q + (h*LR + l)*NS*DHH;
    __nv_bfloat16* qp = q_pk + (size_t)(h*LR + l)*QK_KP;
    for(int idx=tid; idx<NS*DHH; idx+=256){
        float xx = qb[idx]*wsh[idx>>5];
        __nv_bfloat16 hi, lo; bsplit(xx, hi, lo);
        qp[idx] = hi; qp[idx + 8192] = hi; qp[idx + 16384] = lo;
    }
}

// ---------------- 6. bias = LN(pair) @ wb ----------------
__global__ void bias_kernel(const float* __restrict__ pair, const float* __restrict__ g,
                            const float* __restrict__ b, const float* __restrict__ wb){
    __shared__ float wbs[NH][DP];
    int tid = threadIdx.x;
    for(int idx=tid; idx<NH*DP; idx+=256){
        int h = idx / DP, k = idx % DP;
        wbs[h][k] = wb[k*NH + h];
    }
    __syncthreads();
    int warp = tid >> 5, lane = tid & 31;
    int p = blockIdx.x*8 + warp;
    float4 xv = ((const float4*)(pair + p*DP))[lane];
    float sum = xv.x+xv.y+xv.z+xv.w;
    float sq  = xv.x*xv.x+xv.y*xv.y+xv.z*xv.z+xv.w*xv.w;
    sum = warpRed(sum); sq = warpRed(sq);
    float mean = sum*(1.f/DP);
    float var  = sq*(1.f/DP) - mean*mean;
    float inv  = rsqrtf(var + 1e-5f);
    float4 gv = ((const float4*)g)[lane];
    float4 bv = ((const float4*)b)[lane];
    float xn0 = (xv.x-mean)*inv*gv.x + bv.x;
    float xn1 = (xv.y-mean)*inv*gv.y + bv.y;
    float xn2 = (xv.z-mean)*inv*gv.z + bv.z;
    float xn3 = (xv.w-mean)*inv*gv.w + bv.w;
    #pragma unroll
    for(int h=0;h<NH;h++){
        float4 wv4 = ((const float4*)(wbs[h]))[lane];
        float prt = xn0*wv4.x + xn1*wv4.y + xn2*wv4.z + xn3*wv4.w;
        prt = warpRed(prt);
        if(lane==0) g_bias[h*LL + p] = prt;
    }
}

// ---------------- 8. softmax over k (+ bias) -> packed P ----------------
__global__ void attn_softmax_kernel(){
    __shared__ float sh[4];
    int row = blockIdx.x;   // h*LR + q
    const float* a = g_attn + row*LR;
    const float* bi = g_bias + row*LR;
    int tid = threadIdx.x;  // 128 threads
    float x0 = a[tid]       + bi[tid];
    float x1 = a[tid+128]   + bi[tid+128];
    float x2 = a[tid+256]   + bi[tid+256];
    float m = fmaxf(x0, fmaxf(x1, x2));
    m = warpMax(m);
    if((tid&31)==0) sh[tid>>5]=m;
    __syncthreads();
    if(tid<32){ float mm=(tid<4)?sh[tid]:-1e30f; mm=warpMax(mm); if(tid==0) sh[0]=mm; }
    __syncthreads();
    m = sh[0];
    __syncthreads();
    x0 = expf(x0-m); x1 = expf(x1-m); x2 = expf(x2-m);
    float s = warpRed(x0+x1+x2);
    if((tid&31)==0) sh[tid>>5]=s;
    __syncthreads();
    if(tid<32){ float ss=(tid<4)?sh[tid]:0.f; ss=warpRed(ss); if(tid==0) sh[0]=ss; }
    __syncthreads();
    s = sh[0];
    float rcp = 1.f/s;
    __nv_bfloat16* pp = p_pk + (size_t)row*AV_KP;
    __nv_bfloat16 hi, lo;
    bsplit(x0*rcp, hi, lo); pp[tid]     = hi; pp[tid+LR]     = hi; pp[tid+2*LR]     = lo;
    bsplit(x1*rcp, hi, lo); pp[tid+128] = hi; pp[tid+128+LR] = hi; pp[tid+128+2*LR] = lo;
    bsplit(x2*rcp, hi, lo); pp[tid+256] = hi; pp[tid+256+LR] = hi; pp[tid+256+2*LR] = lo;
}

// ---------------- launch ----------------
extern "C" void kernel_launch(void* const* d_in, const int* in_sizes, int n_in,
                              void* d_out, int out_size){
    const float* msa       = (const float*)d_in[0];
    const float* pair      = (const float*)d_in[1];
    const float* ln_msa_g  = (const float*)d_in[2];
    const float* ln_msa_b  = (const float*)d_in[3];
    const float* ln_pair_g = (const float*)d_in[4];
    const float* ln_pair_b = (const float*)d_in[5];
    const float* sw_q_w    = (const float*)d_in[6];
    const float* sw_q_b    = (const float*)d_in[7];
    const float* sw_k_w    = (const float*)d_in[8];
    const float* sw_k_b    = (const float*)d_in[9];
    const float* wq        = (const float*)d_in[10];
    const float* wk        = (const float*)d_in[11];
    const float* wv        = (const float*)d_in[12];
    const float* wb        = (const float*)d_in[13];
    const float* wg        = (const float*)d_in[14];
    const float* bg        = (const float*)d_in[15];
    const float* wo        = (const float*)d_in[16];
    const float* bo        = (const float*)d_in[17];
    float* out = (float*)d_out;

    ln_msa_kernel<<<NL, 256>>>(msa, ln_msa_g, ln_msa_b);
    pack_w_kernel<<<1280, 256>>>(wq, wk, wv, wg, sw_k_w);
    pack_wo_kernel<<<256, 256>>>(wo);
    swq_kernel<<<LR, 256>>>(sw_q_w, sw_q_b);
    zero_attn_kernel<<<(NH*LL+1023)/1024, 1024>>>();

    // proj: [98304 x 1280], K'=768
    gemm_mma<0><<<dim3(10, 768, 1), 256>>>(bg, sw_k_b, nullptr);

    logit_kernel<<<NL/8, 256>>>();
    seq_softmax_kernel<<<LR*NH, 256>>>();
    bias_kernel<<<LL/8, 256>>>(pair, ln_pair_g, ln_pair_b, wb);

    // qk: per head [384 x 384], K'=24576, split-K x4 -> atomicAdd
    gemm_mma<1><<<dim3(3, 3, NH*4), 256>>>(nullptr, nullptr, nullptr);

    attn_softmax_kernel<<<NH*LR, 128>>>();

    // av: per head [384 x 8192], K'=1152
    gemm_mma<2><<<dim3(64, 3, NH), 256>>>(nullptr, nullptr, nullptr);

    // out: [98304 x 256], K'=768
    gemm_mma<3><<<dim3(2, 768, 1), 256>>>(bo, nullptr, out);
}

// round 6
// speedup vs baseline: 1.9712x; 1.0702x over previous
#include <cuda_runtime.h>
#include <cuda_bf16.h>
#include <math.h>
#include <stdint.h>

// Problem constants
#define NS 256
#define LR 384
#define DM 256
#define DP 128
#define NH 8
#define DHH 32
#define HDM 256
#define NL (NS*LR)      // 98304
#define LL (LR*LR)      // 147456
#define SCALE_DH 0.17677669529663687f

#define PJ_KP 768       // 3*256
#define QK_KP 24576     // 3*8192
#define AV_KP 1152      // 3*384

// ---------------- device scratch ----------------
__device__ float g_msan[NL*DM];
__device__ float g_swq[LR*HDM];
__device__ float g_swk[NL*HDM];
__device__ float g_q[NH*LR*NS*DHH];       // raw q, [h][l][n][d]
__device__ float g_gate[NL*HDM];
__device__ float g_logit[LR*NH*NS];
__device__ float g_bias[NH*LL];
__device__ float g_attn[NH*LL];           // qk logits (accumulated via atomics)

// packed bf16 operands (A pattern = [hi|hi|lo], B pattern = [hi|lo|hi] along K)
__device__ __nv_bfloat16 a_pk[(size_t)NL*PJ_KP];
__device__ __nv_bfloat16 b_pk[1280*PJ_KP];
__device__ __nv_bfloat16 wo_pk[DM*PJ_KP];
__device__ __nv_bfloat16 q_pk[(size_t)NH*LR*QK_KP];
__device__ __nv_bfloat16 k_pk[(size_t)NH*LR*QK_KP];
__device__ __nv_bfloat16 vt_pk[(size_t)NH*NS*DHH*AV_KP];
__device__ __nv_bfloat16 p_pk[(size_t)NH*LR*AV_KP];

// ---------------- helpers ----------------
__device__ __forceinline__ float warpRed(float v){
    #pragma unroll
    for(int o=16;o>0;o>>=1) v += __shfl_xor_sync(0xffffffffu, v, o);
    return v;
}
__device__ __forceinline__ float warpMax(float v){
    #pragma unroll
    for(int o=16;o>0;o>>=1) v = fmaxf(v, __shfl_xor_sync(0xffffffffu, v, o));
    return v;
}
__device__ __forceinline__ void bsplit(float x, __nv_bfloat16& h, __nv_bfloat16& l){
    h = __float2bfloat16(x);
    l = __float2bfloat16(x - __bfloat162float(h));
}
__device__ __forceinline__ uint32_t s2u(const void* p){
    uint32_t a; asm("{ .reg .u64 t; cvta.to.shared.u64 t, %1; cvt.u32.u64 %0, t; }" : "=r"(a) : "l"(p));
    return a;
}

// ---------------- 1. LayerNorm of msa + pack A ----------------
__global__ void ln_msa_kernel(const float* __restrict__ x,
                              const float* __restrict__ gg,
                              const float* __restrict__ bb){
    __shared__ float s1[8], s2[8];
    int row = blockIdx.x, tid = threadIdx.x;
    float v = x[row*DM + tid];
    float a = warpRed(v);
    float b = warpRed(v*v);
    if((tid&31)==0){ s1[tid>>5]=a; s2[tid>>5]=b; }
    __syncthreads();
    if(tid<32){
        float aa = (tid<8)? s1[tid] : 0.f;
        float bb2 = (tid<8)? s2[tid] : 0.f;
        aa = warpRed(aa); bb2 = warpRed(bb2);
        if(tid==0){ s1[0]=aa; s2[0]=bb2; }
    }
    __syncthreads();
    float mean = s1[0]*(1.f/DM);
    float var  = s2[0]*(1.f/DM) - mean*mean;
    float inv  = rsqrtf(var + 1e-5f);
    float y = (v-mean)*inv*gg[tid] + bb[tid];
    g_msan[row*DM + tid] = y;
    __nv_bfloat16 hi, lo; bsplit(y, hi, lo);
    size_t base = (size_t)row*PJ_KP;
    a_pk[base + tid]       = hi;
    a_pk[base + 256 + tid] = hi;
    a_pk[base + 512 + tid] = lo;
}

// ---------------- 2. pack weights ----------------
__global__ void pack_w_kernel(const float* __restrict__ wq, const float* __restrict__ wk,
                              const float* __restrict__ wv, const float* __restrict__ wg,
                              const float* __restrict__ wsk){
    int n = blockIdx.x, k = threadIdx.x;
    int mat = n >> 8, nl = n & 255;
    const float* W = (mat==0)?wq:(mat==1)?wk:(mat==2)?wv:(mat==3)?wg:wsk;
    float x = W[k*HDM + nl];
    __nv_bfloat16 hi, lo; bsplit(x, hi, lo);
    int base = n*PJ_KP;
    b_pk[base + k]       = hi;
    b_pk[base + 256 + k] = lo;
    b_pk[base + 512 + k] = hi;
}
__global__ void pack_wo_kernel(const float* __restrict__ wo){
    int n = blockIdx.x, k = threadIdx.x;
    float x = wo[k*DM + n];
    __nv_bfloat16 hi, lo; bsplit(x, hi, lo);
    int base = n*PJ_KP;
    wo_pk[base + k]       = hi;
    wo_pk[base + 256 + k] = lo;
    wo_pk[base + 512 + k] = hi;
}

// ---------------- 3. swq ----------------
__global__ void swq_kernel(const float* __restrict__ W, const float* __restrict__ bqb){
    __shared__ float t[DM];
    int l = blockIdx.x, tid = threadIdx.x;
    t[tid] = g_msan[l*DM + tid];
    __syncthreads();
    float acc = 0.f;
    #pragma unroll 8
    for(int k=0;k<DM;k++) acc += t[k]*W[k*HDM + tid];
    g_swq[l*HDM + tid] = (acc + bqb[tid]) * SCALE_DH;
}

// ---------------- zero g_attn (for split-K atomics) ----------------
__global__ void zero_attn_kernel(){
    int i = blockIdx.x*1024 + threadIdx.x;
    if(i < NH*LL) g_attn[i] = 0.f;
}

// ---------------- mma.sync bf16 GEMM, BK=64, 3-stage cp.async ----------------
// C[row,col] = sum_k A[row,k]*B[col,k], both K-major bf16.
// 256 thr / 8 warps. BM=BN=128, BK=64. Warp tile 32x64.
// MODE 0: proj; MODE 1: qk (split-K x4, atomicAdd); MODE 2: av; MODE 3: out.
#define RPITCH 72                       // bf16 per SMEM row (144 B, conflict-free)
#define STG_ELEM (256*RPITCH)           // A(128 rows)+B(128 rows) per stage
#define STG_BYTES (STG_ELEM*2)          // 36864
#define B_OFF_BYTES (128*RPITCH*2)      // 18432
#define NSTAGE 3
#define GSMEM_BYTES (NSTAGE*STG_BYTES)  // 110592

template<int MODE>
__device__ __forceinline__ void epi(int R, int Cg, float v, int zz,
        const float* __restrict__ p0, const float* __restrict__ p1,
        float* __restrict__ outp){
    if(MODE==0){
        int n = R/LR, l = R - n*LR;
        int matq = Cg>>8, cl = Cg&255, h = cl>>5, d = cl&31;
        if(matq==0) g_q[((h*LR+l)*NS+n)*DHH + d] = v;
        else if(matq==1){ __nv_bfloat16 hi,lo; bsplit(v*SCALE_DH,hi,lo);
            int bi=(h*LR+l)*QK_KP + n*DHH + d;
            k_pk[bi]=hi; k_pk[bi+8192]=lo; k_pk[bi+16384]=hi; }
        else if(matq==2){ __nv_bfloat16 hi,lo; bsplit(v,hi,lo);
            int bi=(h*NS*DHH+n*DHH+d)*AV_KP + l;
            vt_pk[bi]=hi; vt_pk[bi+LR]=lo; vt_pk[bi+2*LR]=hi; }
        else if(matq==3) g_gate[R*HDM+cl] = 1.f/(1.f+expf(-(v+p0[cl])));
        else g_swk[R*HDM+cl] = v + p1[cl];
    } else if(MODE==1){
        atomicAdd(&g_attn[zz*LL + R*LR + Cg], v);
    } else if(MODE==2){
        int s = Cg>>5, d = Cg&31;
        int rr = s*LR + R;
        float g = g_gate[rr*HDM + zz*DHH + d];
        __nv_bfloat16 hi,lo; bsplit(v*g,hi,lo);
        size_t bi = (size_t)rr*PJ_KP + zz*DHH + d;
        a_pk[bi]=hi; a_pk[bi+256]=hi; a_pk[bi+512]=lo;
    } else {
        outp[R*DM+Cg] = v + p0[Cg];
    }
}

template<int MODE>
__global__ __launch_bounds__(256)
void gemm_mma(const float* __restrict__ p0, const float* __restrict__ p1,
              float* __restrict__ outp){
    constexpr int Kp = (MODE==1) ? QK_KP : (MODE==2) ? AV_KP : PJ_KP;
    extern __shared__ __nv_bfloat16 smem[];
    const uint32_t sbase = s2u(smem);

    const int tid = threadIdx.x, wid = tid>>5, lane = tid&31;
    const int wm = wid & 3, wn = wid >> 2;
    const int nt = blockIdx.x, mt = blockIdx.y, z = blockIdx.z;

    const __nv_bfloat16* A; const __nv_bfloat16* B;
    size_t saz = 0, sbz = 0;
    if(MODE==0){ A = a_pk;  B = b_pk; }
    else if(MODE==1){ A = q_pk; B = k_pk; saz = (size_t)LR*QK_KP; sbz = saz; }
    else if(MODE==2){ A = p_pk; B = vt_pk; saz = (size_t)LR*AV_KP; sbz = (size_t)NS*DHH*AV_KP; }
    else { A = a_pk; B = wo_pk; }

    int zz = z, koff = 0;
    int Cn = Kp/64;
    if(MODE==1){ zz = z>>2; koff = (z&3)*(Kp/4); Cn = Kp/256; }

    const __nv_bfloat16* Ab = A + saz*zz + (size_t)(mt*128)*Kp + koff;
    const __nv_bfloat16* Bb = B + sbz*zz + (size_t)(nt*128)*Kp + koff;

    float acc[2][8][4];
    #pragma unroll
    for(int i=0;i<2;i++)
        #pragma unroll
        for(int j=0;j<8;j++)
            #pragma unroll
            for(int k=0;k<4;k++) acc[i][j][k]=0.f;

    // per-thread static load coords: t=0..3 -> A rows, t=4..7 -> B rows
    // idx = tid + t*256 ; r = (idx & 1023)>>3 ; cc = idx&7
    auto issue_stage = [&](int c){
        const uint32_t stg = sbase + (uint32_t)(c % NSTAGE)*STG_BYTES;
        const __nv_bfloat16* ac = Ab + c*64;
        const __nv_bfloat16* bc = Bb + c*64;
        #pragma unroll
        for(int t=0;t<4;t++){
            int idx = tid + t*256;
            int r = idx>>3, cc = idx&7;
            uint32_t sa = stg + r*144 + cc*16;
            const void* ga = ac + (size_t)r*Kp + cc*8;
            asm volatile("cp.async.cg.shared.global [%0], [%1], 16;"::"r"(sa),"l"(ga));
        }
        #pragma unroll
        for(int t=0;t<4;t++){
            int idx = tid + t*256 - 1024 + 1024; // t=4..7 mapped below
            idx = tid + (t+4)*256 - 1024;
            int r = idx>>3, cc = idx&7;
            uint32_t sb = stg + B_OFF_BYTES + r*144 + cc*16;
            const void* gb = bc + (size_t)r*Kp + cc*8;
            asm volatile("cp.async.cg.shared.global [%0], [%1], 16;"::"r"(sb),"l"(gb));
        }
        asm volatile("cp.async.commit_group;");
    };

    // prologue: 2 stages in flight
    issue_stage(0);
    if(Cn > 1) issue_stage(1);

    for(int c = 0; c < Cn; c++){
        if(c < Cn-1) asm volatile("cp.async.wait_group 1;");
        else         asm volatile("cp.async.wait_group 0;");
        __syncthreads();
        if(c+2 < Cn) issue_stage(c+2);

        const uint32_t stg = sbase + (uint32_t)(c % NSTAGE)*STG_BYTES;
        const uint32_t abase = stg;
        const uint32_t bbase = stg + B_OFF_BYTES;
        #pragma unroll
        for(int ks=0; ks<4; ks++){
            uint32_t ar[2][4];
            #pragma unroll
            for(int mi=0;mi<2;mi++){
                int row = wm*32 + mi*16 + (lane&15);
                uint32_t addr = abase + row*144 + ks*32 + (lane>>4)*16;
                asm volatile("ldmatrix.sync.aligned.m8n8.x4.shared.b16 {%0,%1,%2,%3}, [%4];"
                    : "=r"(ar[mi][0]),"=r"(ar[mi][1]),"=r"(ar[mi][2]),"=r"(ar[mi][3])
                    : "r"(addr));
            }
            uint32_t br[4][4];
            #pragma unroll
            for(int nb=0;nb<4;nb++){
                int nrow = wn*64 + nb*16 + (lane&7) + ((lane>>4)&1)*8;
                uint32_t addr = bbase + nrow*144 + ks*32 + ((lane>>3)&1)*16;
                asm volatile("ldmatrix.sync.aligned.m8n8.x4.shared.b16 {%0,%1,%2,%3}, [%4];"
                    : "=r"(br[nb][0]),"=r"(br[nb][1]),"=r"(br[nb][2]),"=r"(br[nb][3])
                    : "r"(addr));
            }
            #pragma unroll
            for(int mi=0;mi<2;mi++)
                #pragma unroll
                for(int ni=0;ni<8;ni++){
                    uint32_t b0 = br[ni>>1][(ni&1)*2];
                    uint32_t b1 = br[ni>>1][(ni&1)*2+1];
                    float* cc2 = acc[mi][ni];
                    asm volatile(
                        "mma.sync.aligned.m16n8k16.row.col.f32.bf16.bf16.f32 "
                        "{%0,%1,%2,%3}, {%4,%5,%6,%7}, {%8,%9}, {%0,%1,%2,%3};"
                        : "+f"(cc2[0]),"+f"(cc2[1]),"+f"(cc2[2]),"+f"(cc2[3])
                        : "r"(ar[mi][0]),"r"(ar[mi][1]),"r"(ar[mi][2]),"r"(ar[mi][3]),
                          "r"(b0),"r"(b1));
                }
        }
        __syncthreads();
    }

    // epilogue
    const int grow = lane>>2, gcol = (lane&3)*2;
    #pragma unroll
    for(int mi=0;mi<2;mi++){
        #pragma unroll
        for(int ni=0;ni<8;ni++){
            int R0 = mt*128 + wm*32 + mi*16 + grow;
            int C0 = nt*128 + wn*64 + ni*8 + gcol;
            epi<MODE>(R0,   C0,   acc[mi][ni][0], zz, p0, p1, outp);
            epi<MODE>(R0,   C0+1, acc[mi][ni][1], zz, p0, p1, outp);
            epi<MODE>(R0+8, C0,   acc[mi][ni][2], zz, p0, p1, outp);
            epi<MODE>(R0+8, C0+1, acc[mi][ni][3], zz, p0, p1, outp);
        }
    }
}

// ---------------- 4. sw logits ----------------
__global__ void logit_kernel(){
    int warp = threadIdx.x >> 5, lane = threadIdx.x & 31;
    int r = blockIdx.x*8 + warp;
    int n = r / LR, l = r % LR;
    const float* swkrow = g_swk + r*HDM;
    const float* swqrow = g_swq + l*HDM;
    #pragma unroll
    for(int h=0;h<NH;h++){
        float p = swqrow[h*32+lane]*swkrow[h*32+lane];
        p = warpRed(p);
        if(lane==0) g_logit[(l*NH+h)*NS + n] = p;
    }
}

// ---------------- 5. softmax over n + packed weighted q ----------------
__global__ void seq_softmax_kernel(){
    __shared__ float sh[8];
    __shared__ float wsh[NS];
    int l = blockIdx.x >> 3, h = blockIdx.x & 7;
    int tid = threadIdx.x;
    float x = g_logit[(l*NH+h)*NS + tid];
    float m = warpMax(x);
    if((tid&31)==0) sh[tid>>5]=m;
    __syncthreads();
    if(tid<32){ float mm=(tid<8)?sh[tid]:-1e30f; mm=warpMax(mm); if(tid==0) sh[0]=mm; }
    __syncthreads();
    m = sh[0];
    __syncthreads();
    float e = expf(x - m);
    float s = warpRed(e);
    if((tid&31)==0) sh[tid>>5]=s;
    __syncthreads();
    if(tid<32){ float ss=(tid<8)?sh[tid]:0.f; ss=warpRed(ss); if(tid==0) sh[0]=ss; }
    __syncthreads();
    s = sh[0];
    wsh[tid] = e / s;
    __syncthreads();
    const float* qb = g_q + (h*LR + l)*NS*DHH;
    __nv_bfloat16* qp = q_pk + (size_t)(h*LR + l)*QK_KP;
    for(int idx=tid; idx<NS*DHH; idx+=256){
        float xx = qb[idx]*wsh[idx>>5];
        __nv_bfloat16 hi, lo; bsplit(xx, hi, lo);
        qp[idx] = hi; qp[idx + 8192] = hi; qp[idx + 16384] = lo;
    }
}

// ---------------- 6. bias = LN(pair) @ wb ----------------
__global__ void bias_kernel(const float* __restrict__ pair, const float* __restrict__ g,
                            const float* __restrict__ b, const float* __restrict__ wb){
    __shared__ float wbs[NH][DP];
    int tid = threadIdx.x;
    for(int idx=tid; idx<NH*DP; idx+=256){
        int h = idx / DP, k = idx % DP;
        wbs[h][k] = wb[k*NH + h];
    }
    __syncthreads();
    int warp = tid >> 5, lane = tid & 31;
    int p = blockIdx.x*8 + warp;
    float4 xv = ((const float4*)(pair + p*DP))[lane];
    float sum = xv.x+xv.y+xv.z+xv.w;
    float sq  = xv.x*xv.x+xv.y*xv.y+xv.z*xv.z+xv.w*xv.w;
    sum = warpRed(sum); sq = warpRed(sq);
    float mean = sum*(1.f/DP);
    float var  = sq*(1.f/DP) - mean*mean;
    float inv  = rsqrtf(var + 1e-5f);
    float4 gv = ((const float4*)g)[lane];
    float4 bv = ((const float4*)b)[lane];
    float xn0 = (xv.x-mean)*inv*gv.x + bv.x;
    float xn1 = (xv.y-mean)*inv*gv.y + bv.y;
    float xn2 = (xv.z-mean)*inv*gv.z + bv.z;
    float xn3 = (xv.w-mean)*inv*gv.w + bv.w;
    #pragma unroll
    for(int h=0;h<NH;h++){
        float4 wv4 = ((const float4*)(wbs[h]))[lane];
        float prt = xn0*wv4.x + xn1*wv4.y + xn2*wv4.z + xn3*wv4.w;
        prt = warpRed(prt);
        if(lane==0) g_bias[h*LL + p] = prt;
    }
}

// ---------------- 8. softmax over k (+ bias) -> packed P ----------------
__global__ void attn_softmax_kernel(){
    __shared__ float sh[4];
    int row = blockIdx.x;   // h*LR + q
    const float* a = g_attn + row*LR;
    const float* bi = g_bias + row*LR;
    int tid = threadIdx.x;  // 128 threads
    float x0 = a[tid]       + bi[tid];
    float x1 = a[tid+128]   + bi[tid+128];
    float x2 = a[tid+256]   + bi[tid+256];
    float m = fmaxf(x0, fmaxf(x1, x2));
    m = warpMax(m);
    if((tid&31)==0) sh[tid>>5]=m;
    __syncthreads();
    if(tid<32){ float mm=(tid<4)?sh[tid]:-1e30f; mm=warpMax(mm); if(tid==0) sh[0]=mm; }
    __syncthreads();
    m = sh[0];
    __syncthreads();
    x0 = expf(x0-m); x1 = expf(x1-m); x2 = expf(x2-m);
    float s = warpRed(x0+x1+x2);
    if((tid&31)==0) sh[tid>>5]=s;
    __syncthreads();
    if(tid<32){ float ss=(tid<4)?sh[tid]:0.f; ss=warpRed(ss); if(tid==0) sh[0]=ss; }
    __syncthreads();
    s = sh[0];
    float rcp = 1.f/s;
    __nv_bfloat16* pp = p_pk + (size_t)row*AV_KP;
    __nv_bfloat16 hi, lo;
    bsplit(x0*rcp, hi, lo); pp[tid]     = hi; pp[tid+LR]     = hi; pp[tid+2*LR]     = lo;
    bsplit(x1*rcp, hi, lo); pp[tid+128] = hi; pp[tid+128+LR] = hi; pp[tid+128+2*LR] = lo;
    bsplit(x2*rcp, hi, lo); pp[tid+256] = hi; pp[tid+256+LR] = hi; pp[tid+256+2*LR] = lo;
}

// ---------------- launch ----------------
extern "C" void kernel_launch(void* const* d_in, const int* in_sizes, int n_in,
                              void* d_out, int out_size){
    const float* msa       = (const float*)d_in[0];
    const float* pair      = (const float*)d_in[1];
    const float* ln_msa_g  = (const float*)d_in[2];
    const float* ln_msa_b  = (const float*)d_in[3];
    const float* ln_pair_g = (const float*)d_in[4];
    const float* ln_pair_b = (const float*)d_in[5];
    const float* sw_q_w    = (const float*)d_in[6];
    const float* sw_q_b    = (const float*)d_in[7];
    const float* sw_k_w    = (const float*)d_in[8];
    const float* sw_k_b    = (const float*)d_in[9];
    const float* wq        = (const float*)d_in[10];
    const float* wk        = (const float*)d_in[11];
    const float* wv        = (const float*)d_in[12];
    const float* wb        = (const float*)d_in[13];
    const float* wg        = (const float*)d_in[14];
    const float* bg        = (const float*)d_in[15];
    const float* wo        = (const float*)d_in[16];
    const float* bo        = (const float*)d_in[17];
    float* out = (float*)d_out;

    cudaFuncSetAttribute(gemm_mma<0>, cudaFuncAttributeMaxDynamicSharedMemorySize, GSMEM_BYTES);
    cudaFuncSetAttribute(gemm_mma<1>, cudaFuncAttributeMaxDynamicSharedMemorySize, GSMEM_BYTES);
    cudaFuncSetAttribute(gemm_mma<2>, cudaFuncAttributeMaxDynamicSharedMemorySize, GSMEM_BYTES);
    cudaFuncSetAttribute(gemm_mma<3>, cudaFuncAttributeMaxDynamicSharedMemorySize, GSMEM_BYTES);

    ln_msa_kernel<<<NL, 256>>>(msa, ln_msa_g, ln_msa_b);
    pack_w_kernel<<<1280, 256>>>(wq, wk, wv, wg, sw_k_w);
    pack_wo_kernel<<<256, 256>>>(wo);
    swq_kernel<<<LR, 256>>>(sw_q_w, sw_q_b);
    zero_attn_kernel<<<(NH*LL+1023)/1024, 1024>>>();

    // proj: [98304 x 1280], K'=768
    gemm_mma<0><<<dim3(10, 768, 1), 256, GSMEM_BYTES>>>(bg, sw_k_b, nullptr);

    logit_kernel<<<NL/8, 256>>>();
    seq_softmax_kernel<<<LR*NH, 256>>>();
    bias_kernel<<<LL/8, 256>>>(pair, ln_pair_g, ln_pair_b, wb);

    // qk: per head [384 x 384], K'=24576, split-K x4 -> atomicAdd
    gemm_mma<1><<<dim3(3, 3, NH*4), 256, GSMEM_BYTES>>>(nullptr, nullptr, nullptr);

    attn_softmax_kernel<<<NH*LR, 128>>>();

    // av: per head [384 x 8192], K'=1152
    gemm_mma<2><<<dim3(64, 3, NH), 256, GSMEM_BYTES>>>(nullptr, nullptr, nullptr);

    // out: [98304 x 256], K'=768
    gemm_mma<3><<<dim3(2, 768, 1), 256, GSMEM_BYTES>>>(bo, nullptr, out);
}

// round 7
// speedup vs baseline: 2.4519x; 1.2438x over previous
#include <cuda_runtime.h>
#include <cuda_fp16.h>
#include <math.h>
#include <stdint.h>

// Problem constants
#define NS 256
#define LR 384
#define DM 256
#define DP 128
#define NH 8
#define DHH 32
#define HDM 256
#define NL (NS*LR)      // 98304
#define LL (LR*LR)      // 147456
#define SCALE_DH 0.17677669529663687f

// ---------------- device scratch ----------------
__device__ float g_msan[NL*DM];
__device__ float g_swq[LR*HDM];
__device__ float g_swk[NL*HDM];
__device__ float g_q[NH*LR*NS*DHH];       // raw q, [h][l][n][d]
__device__ float g_gate[NL*HDM];
__device__ float g_logit[LR*NH*NS];
__device__ float g_bias[NH*LL];
__device__ float g_attn[NH*LL];           // qk logits (split-K atomics)

// packed fp16 operands. A-side = [hi | lo] (2x K). B-side = single fp16 (read twice).
__device__ __half a_pk[(size_t)NL*512];            // msan / gated-out, [r][512]
__device__ __half b_pk[1280*256];                  // proj weights^T, [n][256]
__device__ __half wo_pk[DM*256];                   // wo^T, [n][256]
__device__ __half q_pk[(size_t)NH*LR*16384];       // [h*384+l][hi8192|lo8192]
__device__ __half k_pk[(size_t)NH*LR*8192];        // [h*384+l][n*32+d]
__device__ __half vt_pk[(size_t)NH*NS*DHH*LR];     // [h*8192+(s*32+d)][l]
__device__ __half p_pk[(size_t)NH*LR*768];         // [h*384+q][hi384|lo384]

// ---------------- helpers ----------------
__device__ __forceinline__ float warpRed(float v){
    #pragma unroll
    for(int o=16;o>0;o>>=1) v += __shfl_xor_sync(0xffffffffu, v, o);
    return v;
}
__device__ __forceinline__ float warpMax(float v){
    #pragma unroll
    for(int o=16;o>0;o>>=1) v = fmaxf(v, __shfl_xor_sync(0xffffffffu, v, o));
    return v;
}
__device__ __forceinline__ void hsplit(float x, __half& h, __half& l){
    h = __float2half(x);
    l = __float2half(x - __half2float(h));
}
__device__ __forceinline__ uint32_t s2u(const void* p){
    uint32_t a; asm("{ .reg .u64 t; cvta.to.shared.u64 t, %1; cvt.u32.u64 %0, t; }" : "=r"(a) : "l"(p));
    return a;
}

// ---------------- 1. LayerNorm of msa + pack A [hi|lo] ----------------
__global__ void ln_msa_kernel(const float* __restrict__ x,
                              const float* __restrict__ gg,
                              const float* __restrict__ bb){
    __shared__ float s1[8], s2[8];
    int row = blockIdx.x, tid = threadIdx.x;
    float v = x[row*DM + tid];
    float a = warpRed(v);
    float b = warpRed(v*v);
    if((tid&31)==0){ s1[tid>>5]=a; s2[tid>>5]=b; }
    __syncthreads();
    if(tid<32){
        float aa = (tid<8)? s1[tid] : 0.f;
        float bb2 = (tid<8)? s2[tid] : 0.f;
        aa = warpRed(aa); bb2 = warpRed(bb2);
        if(tid==0){ s1[0]=aa; s2[0]=bb2; }
    }
    __syncthreads();
    float mean = s1[0]*(1.f/DM);
    float var  = s2[0]*(1.f/DM) - mean*mean;
    float inv  = rsqrtf(var + 1e-5f);
    float y = (v-mean)*inv*gg[tid] + bb[tid];
    g_msan[row*DM + tid] = y;
    __half hi, lo; hsplit(y, hi, lo);
    size_t base = (size_t)row*512;
    a_pk[base + tid]       = hi;
    a_pk[base + 256 + tid] = lo;
}

// ---------------- 2. pack weights (transposed, single fp16) ----------------
__global__ void pack_w_kernel(const float* __restrict__ wq, const float* __restrict__ wk,
                              const float* __restrict__ wv, const float* __restrict__ wg,
                              const float* __restrict__ wsk){
    int n = blockIdx.x, k = threadIdx.x;
    int mat = n >> 8, nl = n & 255;
    const float* W = (mat==0)?wq:(mat==1)?wk:(mat==2)?wv:(mat==3)?wg:wsk;
    b_pk[n*256 + k] = __float2half(W[k*HDM + nl]);
}
__global__ void pack_wo_kernel(const float* __restrict__ wo){
    int n = blockIdx.x, k = threadIdx.x;
    wo_pk[n*256 + k] = __float2half(wo[k*DM + n]);
}

// ---------------- 3. swq ----------------
__global__ void swq_kernel(const float* __restrict__ W, const float* __restrict__ bqb){
    __shared__ float t[DM];
    int l = blockIdx.x, tid = threadIdx.x;
    t[tid] = g_msan[l*DM + tid];
    __syncthreads();
    float acc = 0.f;
    #pragma unroll 8
    for(int k=0;k<DM;k++) acc += t[k]*W[k*HDM + tid];
    g_swq[l*HDM + tid] = (acc + bqb[tid]) * SCALE_DH;
}

// ---------------- zero g_attn ----------------
__global__ void zero_attn_kernel(){
    int i = blockIdx.x*1024 + threadIdx.x;
    if(i < NH*LL) g_attn[i] = 0.f;
}

// ---------------- mma.sync fp16 GEMM, A=[hi|lo] 2x split, 3-stage cp.async ----------------
// MODE 0: proj  A=a_pk[NL x 512],      B=b_pk[1280 x 256]   (staged epilogue scatter)
// MODE 1: qk    A=q_pk[h][384x16384],  B=k_pk[h][384x8192]  (split-K x4, atomicAdd)
// MODE 2: av    A=p_pk[h][384x768],    B=vt_pk[h][8192x384] (staged: gate + a_pk)
// MODE 3: out   A=a_pk[NL x 512],      B=wo_pk[256 x 256]   (direct)
#define STG_BYTES 36864                 // (128 A-rows + 128 B-rows) * 144B
#define B_OFF_BYTES 18432
#define NSTAGE 3
#define GSMEM_BYTES (NSTAGE*STG_BYTES)  // 110592

template<int MODE>
__global__ __launch_bounds__(256)
void gemm_mma(const float* __restrict__ p0, const float* __restrict__ p1,
              float* __restrict__ outp){
    constexpr int KR  = (MODE==1) ? 8192 : (MODE==2) ? 384 : 256;  // real K
    constexpr int KPA = 2*KR;                                       // A pitch
    constexpr int KRL = (MODE==1) ? 2048 : KR;                      // local real K
    constexpr int H   = KRL/64;
    constexpr int Cn  = 2*H;

    extern __shared__ char smem[];
    const uint32_t sbase = s2u(smem);

    const int tid = threadIdx.x, wid = tid>>5, lane = tid&31;
    const int wm = wid & 3, wn = wid >> 2;
    const int nt = blockIdx.x, mt = blockIdx.y, z = blockIdx.z;

    const __half* A; const __half* B;
    size_t saz = 0, sbz = 0;
    if(MODE==0){ A = a_pk;  B = b_pk; }
    else if(MODE==1){ A = q_pk; B = k_pk; saz = (size_t)LR*16384; sbz = (size_t)LR*8192; }
    else if(MODE==2){ A = p_pk; B = vt_pk; saz = (size_t)LR*768; sbz = (size_t)NS*DHH*LR; }
    else { A = a_pk; B = wo_pk; }

    const int zz    = (MODE==1) ? (z>>2) : z;
    const int kbase = (MODE==1) ? (z&3)*KRL : 0;

    const __half* Ab = A + saz*zz + (size_t)(mt*128)*KPA;
    const __half* Bb = B + sbz*zz + (size_t)(nt*128)*KR;

    float acc[2][8][4];
    #pragma unroll
    for(int i=0;i<2;i++)
        #pragma unroll
        for(int j=0;j<8;j++)
            #pragma unroll
            for(int k=0;k<4;k++) acc[i][j][k]=0.f;

    auto issue_stage = [&](int c){
        const uint32_t stg = sbase + (uint32_t)(c % NSTAGE)*STG_BYTES;
        const int aoff = (c < H) ? (kbase + c*64) : (KR + kbase + (c-H)*64);
        const int boff = kbase + (c % H)*64;
        const __half* ac = Ab + aoff;
        const __half* bc = Bb + boff;
        #pragma unroll
        for(int t=0;t<4;t++){
            int idx = tid + t*256;
            int r = idx>>3, cc = idx&7;
            uint32_t sa = stg + r*144 + cc*16;
            const void* ga = ac + (size_t)r*KPA + cc*8;
            asm volatile("cp.async.cg.shared.global [%0], [%1], 16;"::"r"(sa),"l"(ga));
        }
        #pragma unroll
        for(int t=0;t<4;t++){
            int idx = tid + t*256;
            int r = idx>>3, cc = idx&7;
            uint32_t sb = stg + B_OFF_BYTES + r*144 + cc*16;
            const void* gb = bc + (size_t)r*KR + cc*8;
            asm volatile("cp.async.cg.shared.global [%0], [%1], 16;"::"r"(sb),"l"(gb));
        }
        asm volatile("cp.async.commit_group;");
    };

    issue_stage(0);
    issue_stage(1);

    for(int c = 0; c < Cn; c++){
        if(c < Cn-1) asm volatile("cp.async.wait_group 1;");
        else         asm volatile("cp.async.wait_group 0;");
        __syncthreads();
        if(c+2 < Cn) issue_stage(c+2);

        const uint32_t stg = sbase + (uint32_t)(c % NSTAGE)*STG_BYTES;
        const uint32_t abase = stg;
        const uint32_t bbase = stg + B_OFF_BYTES;
        #pragma unroll
        for(int ks=0; ks<4; ks++){
            uint32_t ar[2][4];
            #pragma unroll
            for(int mi=0;mi<2;mi++){
                int row = wm*32 + mi*16 + (lane&15);
                uint32_t addr = abase + row*144 + ks*32 + (lane>>4)*16;
                asm volatile("ldmatrix.sync.aligned.m8n8.x4.shared.b16 {%0,%1,%2,%3}, [%4];"
                    : "=r"(ar[mi][0]),"=r"(ar[mi][1]),"=r"(ar[mi][2]),"=r"(ar[mi][3])
                    : "r"(addr));
            }
            uint32_t br[4][4];
            #pragma unroll
            for(int nb=0;nb<4;nb++){
                int nrow = wn*64 + nb*16 + (lane&7) + ((lane>>4)&1)*8;
                uint32_t addr = bbase + nrow*144 + ks*32 + ((lane>>3)&1)*16;
                asm volatile("ldmatrix.sync.aligned.m8n8.x4.shared.b16 {%0,%1,%2,%3}, [%4];"
                    : "=r"(br[nb][0]),"=r"(br[nb][1]),"=r"(br[nb][2]),"=r"(br[nb][3])
                    : "r"(addr));
            }
            #pragma unroll
            for(int mi=0;mi<2;mi++)
                #pragma unroll
                for(int ni=0;ni<8;ni++){
                    uint32_t b0 = br[ni>>1][(ni&1)*2];
                    uint32_t b1 = br[ni>>1][(ni&1)*2+1];
                    float* cc2 = acc[mi][ni];
                    asm volatile(
                        "mma.sync.aligned.m16n8k16.row.col.f32.f16.f16.f32 "
                        "{%0,%1,%2,%3}, {%4,%5,%6,%7}, {%8,%9}, {%0,%1,%2,%3};"
                        : "+f"(cc2[0]),"+f"(cc2[1]),"+f"(cc2[2]),"+f"(cc2[3])
                        : "r"(ar[mi][0]),"r"(ar[mi][1]),"r"(ar[mi][2]),"r"(ar[mi][3]),
                          "r"(b0),"r"(b1));
                }
        }
        __syncthreads();
    }

    const int grow = lane>>2, gcol = (lane&3)*2;

    if(MODE==1){
        #pragma unroll
        for(int mi=0;mi<2;mi++)
            #pragma unroll
            for(int ni=0;ni<8;ni++){
                int R0 = mt*128 + wm*32 + mi*16 + grow;
                int C0 = nt*128 + wn*64 + ni*8 + gcol;
                atomicAdd(&g_attn[zz*LL + R0*LR + C0],       acc[mi][ni][0]);
                atomicAdd(&g_attn[zz*LL + R0*LR + C0+1],     acc[mi][ni][1]);
                atomicAdd(&g_attn[zz*LL + (R0+8)*LR + C0],   acc[mi][ni][2]);
                atomicAdd(&g_attn[zz*LL + (R0+8)*LR + C0+1], acc[mi][ni][3]);
            }
        return;
    }
    if(MODE==3){
        #pragma unroll
        for(int mi=0;mi<2;mi++)
            #pragma unroll
            for(int ni=0;ni<8;ni++){
                int R0 = mt*128 + wm*32 + mi*16 + grow;
                int C0 = nt*128 + wn*64 + ni*8 + gcol;
                outp[R0*DM + C0]       = acc[mi][ni][0] + p0[C0];
                outp[R0*DM + C0+1]     = acc[mi][ni][1] + p0[C0+1];
                outp[(R0+8)*DM + C0]   = acc[mi][ni][2] + p0[C0];
                outp[(R0+8)*DM + C0+1] = acc[mi][ni][3] + p0[C0+1];
            }
        return;
    }

    // staged epilogue (MODE 0 / MODE 2): accumulators -> smem [128][129] fp32
    float* st = (float*)smem;
    #pragma unroll
    for(int mi=0;mi<2;mi++)
        #pragma unroll
        for(int ni=0;ni<8;ni++){
            int r = wm*32 + mi*16 + grow;
            int cc = wn*64 + ni*8 + gcol;
            st[r*129 + cc]       = acc[mi][ni][0];
            st[r*129 + cc+1]     = acc[mi][ni][1];
            st[(r+8)*129 + cc]   = acc[mi][ni][2];
            st[(r+8)*129 + cc+1] = acc[mi][ni][3];
        }
    __syncthreads();

    if(MODE==0){
        const int n  = (mt*128)/LR;
        const int l0 = (mt*128)%LR;
        const int cg0 = nt*128;
        const int matq = cg0>>8;
        const int cl0 = cg0&255;
        if(matq==2){
            // vt_pk: transposed column writes, 128 cols of 128 l-values
            if(tid < 128){
                int cl = cl0 + tid;
                int h = cl>>5, d = cl&31;
                __half* dst = &vt_pk[((size_t)(h*NS*DHH) + n*DHH + d)*LR + l0];
                for(int l=0;l<128;l+=2){
                    __half2 hv = __floats2half2_rn(st[l*129+tid], st[(l+1)*129+tid]);
                    *(__half2*)&dst[l] = hv;
                }
            }
        } else {
            for(int seg = tid; seg < 512; seg += 256){
                int l = seg >> 2, hh = seg & 3;
                int cl = cl0 + hh*32;
                int h = cl>>5;
                const float* srow = &st[l*129 + hh*32];
                if(matq==0){
                    float4* dst = (float4*)&g_q[(((size_t)h*LR + l0+l)*NS + n)*DHH];
                    #pragma unroll
                    for(int d4=0; d4<8; d4++){
                        float4 v4 = make_float4(srow[d4*4],srow[d4*4+1],srow[d4*4+2],srow[d4*4+3]);
                        dst[d4] = v4;
                    }
                } else if(matq==1){
                    __half2* dst = (__half2*)&k_pk[((size_t)h*LR + l0+l)*8192 + n*DHH];
                    #pragma unroll
                    for(int d2=0; d2<16; d2++)
                        dst[d2] = __floats2half2_rn(srow[d2*2]*SCALE_DH, srow[d2*2+1]*SCALE_DH);
                } else if(matq==3){
                    float* dst = &g_gate[(size_t)(n*LR + l0+l)*HDM + cl];
                    #pragma unroll
                    for(int d=0; d<32; d++)
                        dst[d] = 1.f/(1.f + expf(-(srow[d] + p0[cl+d])));
                } else {
                    float* dst = &g_swk[(size_t)(n*LR + l0+l)*HDM + cl];
                    #pragma unroll
                    for(int d=0; d<32; d++)
                        dst[d] = srow[d] + p1[cl+d];
                }
            }
        }
    } else {  // MODE 2: gate + pack into a_pk [hi|lo]
        for(int seg = tid; seg < 512; seg += 256){
            int q = seg>>2, ss = seg&3;
            int s = nt*4 + ss;
            size_t rr = (size_t)s*LR + mt*128 + q;
            const float* gr = &g_gate[rr*HDM + z*DHH];
            const float* srow = &st[q*129 + ss*32];
            __half* dst = &a_pk[rr*512 + z*DHH];
            #pragma unroll
            for(int d=0; d<32; d+=2){
                float v0 = srow[d]*gr[d], v1 = srow[d+1]*gr[d+1];
                __half h0, l0h, h1, l1h;
                hsplit(v0, h0, l0h); hsplit(v1, h1, l1h);
                *(__half2*)&dst[d]       = __halves2half2(h0, h1);
                *(__half2*)&dst[256 + d] = __halves2half2(l0h, l1h);
            }
        }
    }
}

// ---------------- 4. sw logits ----------------
__global__ void logit_kernel(){
    int warp = threadIdx.x >> 5, lane = threadIdx.x & 31;
    int r = blockIdx.x*8 + warp;
    int n = r / LR, l = r % LR;
    const float* swkrow = g_swk + r*HDM;
    const float* swqrow = g_swq + l*HDM;
    #pragma unroll
    for(int h=0;h<NH;h++){
        float p = swqrow[h*32+lane]*swkrow[h*32+lane];
        p = warpRed(p);
        if(lane==0) g_logit[(l*NH+h)*NS + n] = p;
    }
}

// ---------------- 5. softmax over n + packed weighted q [hi|lo] ----------------
__global__ void seq_softmax_kernel(){
    __shared__ float sh[8];
    __shared__ float wsh[NS];
    int l = blockIdx.x >> 3, h = blockIdx.x & 7;
    int tid = threadIdx.x;
    float x = g_logit[(l*NH+h)*NS + tid];
    float m = warpMax(x);
    if((tid&31)==0) sh[tid>>5]=m;
    __syncthreads();
    if(tid<32){ float mm=(tid<8)?sh[tid]:-1e30f; mm=warpMax(mm); if(tid==0) sh[0]=mm; }
    __syncthreads();
    m = sh[0];
    __syncthreads();
    float e = expf(x - m);
    float s = warpRed(e);
    if((tid&31)==0) sh[tid>>5]=s;
    __syncthreads();
    if(tid<32){ float ss=(tid<8)?sh[tid]:0.f; ss=warpRed(ss); if(tid==0) sh[0]=ss; }
    __syncthreads();
    s = sh[0];
    wsh[tid] = e / s;
    __syncthreads();
    const float* qb = g_q + (size_t)(h*LR + l)*NS*DHH;
    __half* qp = q_pk + (size_t)(h*LR + l)*16384;
    for(int idx=tid; idx<NS*DHH; idx+=256){
        float xx = qb[idx]*wsh[idx>>5];
        __half hi, lo; hsplit(xx, hi, lo);
        qp[idx] = hi; qp[idx + 8192] = lo;
    }
}

// ---------------- 6. bias = LN(pair) @ wb ----------------
__global__ void bias_kernel(const float* __restrict__ pair, const float* __restrict__ g,
                            const float* __restrict__ b, const float* __restrict__ wb){
    __shared__ float wbs[NH][DP];
    int tid = threadIdx.x;
    for(int idx=tid; idx<NH*DP; idx+=256){
        int h = idx / DP, k = idx % DP;
        wbs[h][k] = wb[k*NH + h];
    }
    __syncthreads();
    int warp = tid >> 5, lane = tid & 31;
    int p = blockIdx.x*8 + warp;
    float4 xv = ((const float4*)(pair + (size_t)p*DP))[lane];
    float sum = xv.x+xv.y+xv.z+xv.w;
    float sq  = xv.x*xv.x+xv.y*xv.y+xv.z*xv.z+xv.w*xv.w;
    sum = warpRed(sum); sq = warpRed(sq);
    float mean = sum*(1.f/DP);
    float var  = sq*(1.f/DP) - mean*mean;
    float inv  = rsqrtf(var + 1e-5f);
    float4 gv = ((const float4*)g)[lane];
    float4 bv = ((const float4*)b)[lane];
    float xn0 = (xv.x-mean)*inv*gv.x + bv.x;
    float xn1 = (xv.y-mean)*inv*gv.y + bv.y;
    float xn2 = (xv.z-mean)*inv*gv.z + bv.z;
    float xn3 = (xv.w-mean)*inv*gv.w + bv.w;
    #pragma unroll
    for(int h=0;h<NH;h++){
        float4 wv4 = ((const float4*)(wbs[h]))[lane];
        float prt = xn0*wv4.x + xn1*wv4.y + xn2*wv4.z + xn3*wv4.w;
        prt = warpRed(prt);
        if(lane==0) g_bias[h*LL + p] = prt;
    }
}

// ---------------- 8. softmax over k (+ bias) -> packed P [hi|lo] ----------------
__global__ void attn_softmax_kernel(){
    __shared__ float sh[4];
    int row = blockIdx.x;   // h*LR + q
    const float* a = g_attn + (size_t)row*LR;
    const float* bi = g_bias + (size_t)row*LR;
    int tid = threadIdx.x;  // 128 threads
    float x0 = a[tid]       + bi[tid];
    float x1 = a[tid+128]   + bi[tid+128];
    float x2 = a[tid+256]   + bi[tid+256];
    float m = fmaxf(x0, fmaxf(x1, x2));
    m = warpMax(m);
    if((tid&31)==0) sh[tid>>5]=m;
    __syncthreads();
    if(tid<32){ float mm=(tid<4)?sh[tid]:-1e30f; mm=warpMax(mm); if(tid==0) sh[0]=mm; }
    __syncthreads();
    m = sh[0];
    __syncthreads();
    x0 = expf(x0-m); x1 = expf(x1-m); x2 = expf(x2-m);
    float s = warpRed(x0+x1+x2);
    if((tid&31)==0) sh[tid>>5]=s;
    __syncthreads();
    if(tid<32){ float ss=(tid<4)?sh[tid]:0.f; ss=warpRed(ss); if(tid==0) sh[0]=ss; }
    __syncthreads();
    s = sh[0];
    float rcp = 1.f/s;
    __half* pp = p_pk + (size_t)row*768;
    __half hi, lo;
    hsplit(x0*rcp, hi, lo); pp[tid]     = hi; pp[tid+384]     = lo;
    hsplit(x1*rcp, hi, lo); pp[tid+128] = hi; pp[tid+128+384] = lo;
    hsplit(x2*rcp, hi, lo); pp[tid+256] = hi; pp[tid+256+384] = lo;
}

// ---------------- launch ----------------
extern "C" void kernel_launch(void* const* d_in, const int* in_sizes, int n_in,
                              void* d_out, int out_size){
    const float* msa       = (const float*)d_in[0];
    const float* pair      = (const float*)d_in[1];
    const float* ln_msa_g  = (const float*)d_in[2];
    const float* ln_msa_b  = (const float*)d_in[3];
    const float* ln_pair_g = (const float*)d_in[4];
    const float* ln_pair_b = (const float*)d_in[5];
    const float* sw_q_w    = (const float*)d_in[6];
    const float* sw_q_b    = (const float*)d_in[7];
    const float* sw_k_w    = (const float*)d_in[8];
    const float* sw_k_b    = (const float*)d_in[9];
    const float* wq        = (const float*)d_in[10];
    const float* wk        = (const float*)d_in[11];
    const float* wv        = (const float*)d_in[12];
    const float* wb        = (const float*)d_in[13];
    const float* wg        = (const float*)d_in[14];
    const float* bg        = (const float*)d_in[15];
    const float* wo        = (const float*)d_in[16];
    const float* bo        = (const float*)d_in[17];
    float* out = (float*)d_out;

    cudaFuncSetAttribute(gemm_mma<0>, cudaFuncAttributeMaxDynamicSharedMemorySize, GSMEM_BYTES);
    cudaFuncSetAttribute(gemm_mma<1>, cudaFuncAttributeMaxDynamicSharedMemorySize, GSMEM_BYTES);
    cudaFuncSetAttribute(gemm_mma<2>, cudaFuncAttributeMaxDynamicSharedMemorySize, GSMEM_BYTES);
    cudaFuncSetAttribute(gemm_mma<3>, cudaFuncAttributeMaxDynamicSharedMemorySize, GSMEM_BYTES);

    ln_msa_kernel<<<NL, 256>>>(msa, ln_msa_g, ln_msa_b);
    pack_w_kernel<<<1280, 256>>>(wq, wk, wv, wg, sw_k_w);
    pack_wo_kernel<<<256, 256>>>(wo);
    swq_kernel<<<LR, 256>>>(sw_q_w, sw_q_b);
    zero_attn_kernel<<<(NH*LL+1023)/1024, 1024>>>();

    // proj: [98304 x 1280], K'=512
    gemm_mma<0><<<dim3(10, 768, 1), 256, GSMEM_BYTES>>>(bg, sw_k_b, nullptr);

    logit_kernel<<<NL/8, 256>>>();
    seq_softmax_kernel<<<LR*NH, 256>>>();
    bias_kernel<<<LL/8, 256>>>(pair, ln_pair_g, ln_pair_b, wb);

    // qk: per head [384 x 384], K real 8192, split-K x4 -> atomicAdd
    gemm_mma<1><<<dim3(3, 3, NH*4), 256, GSMEM_BYTES>>>(nullptr, nullptr, nullptr);

    attn_softmax_kernel<<<NH*LR, 128>>>();

    // av: per head [384 x 8192], K real 384
    gemm_mma<2><<<dim3(64, 3, NH), 256, GSMEM_BYTES>>>(nullptr, nullptr, nullptr);

    // out: [98304 x 256], K real 256
    gemm_mma<3><<<dim3(2, 768, 1), 256, GSMEM_BYTES>>>(bo, nullptr, out);
}

// round 8
// speedup vs baseline: 2.9625x; 1.2083x over previous
#include <cuda_runtime.h>
#include <cuda_fp16.h>
#include <math.h>
#include <stdint.h>

// Problem constants
#define NS 256
#define LR 384
#define DM 256
#define DP 128
#define NH 8
#define DHH 32
#define HDM 256
#define NL (NS*LR)      // 98304
#define LL (LR*LR)      // 147456
#define SCALE_DH 0.17677669529663687f

// ---------------- device scratch ----------------
__device__ float g_msan[NL*DM];
__device__ float g_swq[LR*HDM];
__device__ float g_lbias[LR*NH];          // sum_d swq[l][h*32+d]*skb[h*32+d]
__device__ float g_gate[NL*HDM];
__device__ float g_logit[LR*NH*NS];
__device__ float g_bias[NH*LL];
__device__ float g_attn[NH*LL];           // qk logits (split-K atomics)

// packed fp16 operands.
__device__ __half a_pk[(size_t)NL*512];            // [r][512]: msan hi (proj) / gated-out [hi|lo] (out)
__device__ __half b_pk[1280*256];                  // proj weights^T, [n][256]
__device__ __half wo_pk[DM*256];                   // wo^T, [n][256]
__device__ __half q_pk[(size_t)NH*LR*8192];        // [h*384+l][n*32+d], raw then weighted
__device__ __half k_pk[(size_t)NH*LR*8192];        // [h*384+l][n*32+d]
__device__ __half vt_pk[(size_t)NH*NS*DHH*LR];     // [h*8192+(s*32+d)][l]
__device__ __half p_pk[(size_t)NH*LR*768];         // [h*384+q][hi384|lo384]

// ---------------- helpers ----------------
__device__ __forceinline__ float warpRed(float v){
    #pragma unroll
    for(int o=16;o>0;o>>=1) v += __shfl_xor_sync(0xffffffffu, v, o);
    return v;
}
__device__ __forceinline__ float warpMax(float v){
    #pragma unroll
    for(int o=16;o>0;o>>=1) v = fmaxf(v, __shfl_xor_sync(0xffffffffu, v, o));
    return v;
}
__device__ __forceinline__ void hsplit(float x, __half& h, __half& l){
    h = __float2half(x);
    l = __float2half(x - __half2float(h));
}
__device__ __forceinline__ uint32_t s2u(const void* p){
    uint32_t a; asm("{ .reg .u64 t; cvta.to.shared.u64 t, %1; cvt.u32.u64 %0, t; }" : "=r"(a) : "l"(p));
    return a;
}

// ---------------- 1. LayerNorm of msa + pack A hi ----------------
__global__ void ln_msa_kernel(const float* __restrict__ x,
                              const float* __restrict__ gg,
                              const float* __restrict__ bb){
    __shared__ float s1[8], s2[8];
    int row = blockIdx.x, tid = threadIdx.x;
    float v = x[row*DM + tid];
    float a = warpRed(v);
    float b = warpRed(v*v);
    if((tid&31)==0){ s1[tid>>5]=a; s2[tid>>5]=b; }
    __syncthreads();
    if(tid<32){
        float aa = (tid<8)? s1[tid] : 0.f;
        float bb2 = (tid<8)? s2[tid] : 0.f;
        aa = warpRed(aa); bb2 = warpRed(bb2);
        if(tid==0){ s1[0]=aa; s2[0]=bb2; }
    }
    __syncthreads();
    float mean = s1[0]*(1.f/DM);
    float var  = s2[0]*(1.f/DM) - mean*mean;
    float inv  = rsqrtf(var + 1e-5f);
    float y = (v-mean)*inv*gg[tid] + bb[tid];
    g_msan[row*DM + tid] = y;
    a_pk[(size_t)row*512 + tid] = __float2half(y);
}

// ---------------- 2. pack weights (transposed, single fp16) ----------------
__global__ void pack_w_kernel(const float* __restrict__ wq, const float* __restrict__ wk,
                              const float* __restrict__ wv, const float* __restrict__ wg,
                              const float* __restrict__ wsk){
    int n = blockIdx.x, k = threadIdx.x;
    int mat = n >> 8, nl = n & 255;
    const float* W = (mat==0)?wq:(mat==1)?wk:(mat==2)?wv:(mat==3)?wg:wsk;
    b_pk[n*256 + k] = __float2half(W[k*HDM + nl]);
}
__global__ void pack_wo_kernel(const float* __restrict__ wo){
    int n = blockIdx.x, k = threadIdx.x;
    wo_pk[n*256 + k] = __float2half(wo[k*DM + n]);
}

// ---------------- 3. swq + lbias ----------------
__global__ void swq_kernel(const float* __restrict__ W, const float* __restrict__ bqb){
    __shared__ float t[DM];
    int l = blockIdx.x, tid = threadIdx.x;
    t[tid] = g_msan[l*DM + tid];
    __syncthreads();
    float acc = 0.f;
    #pragma unroll 8
    for(int k=0;k<DM;k++) acc += t[k]*W[k*HDM + tid];
    g_swq[l*HDM + tid] = (acc + bqb[tid]) * SCALE_DH;
}
__global__ void lbias_kernel(const float* __restrict__ skb){
    int l = blockIdx.x, tid = threadIdx.x, h = tid>>5, lane = tid&31;
    float p = g_swq[l*HDM + tid] * skb[tid];
    p = warpRed(p);
    if(lane==0) g_lbias[l*NH + h] = p;
}

// ---------------- zero g_attn ----------------
__global__ void zero_attn_kernel(){
    int i = blockIdx.x*1024 + threadIdx.x;
    if(i < NH*LL) g_attn[i] = 0.f;
}

// ---------------- mma.sync fp16 GEMM, optional A=[hi|lo] split, 3-stage cp.async ----------------
// MODE 0: proj  A=a_pk hi [NL x 256/512p],  B=b_pk[1280 x 256]   (staged epilogue)
// MODE 1: qk    A=q_pk[h][384x8192],        B=k_pk[h][384x8192]  (split-K x4, atomicAdd)
// MODE 2: av    A=p_pk[h][384x768 hi|lo],   B=vt_pk[h][8192x384] (staged: gate + a_pk)
// MODE 3: out   A=a_pk[NL x 512 hi|lo],     B=wo_pk[256 x 256]   (direct)
#define STG_BYTES 36864                 // (128 A-rows + 128 B-rows) * 144B
#define B_OFF_BYTES 18432
#define NSTAGE 3
#define GSMEM_BYTES (NSTAGE*STG_BYTES)  // 110592

template<int MODE>
__global__ __launch_bounds__(256)
void gemm_mma(const float* __restrict__ p0, const float* __restrict__ p1,
              float* __restrict__ outp){
    constexpr int KR   = (MODE==1) ? 8192 : (MODE==2) ? 384 : 256;  // real K
    constexpr int KPA  = (MODE==1) ? 8192 : (MODE==2) ? 768 : 512;  // A pitch
    constexpr int NSPL = (MODE==2 || MODE==3) ? 2 : 1;              // A split factor
    constexpr int KRL  = (MODE==1) ? 2048 : KR;                     // per-CTA real K
    constexpr int H    = KRL/64;
    constexpr int Cn   = NSPL*H;

    extern __shared__ char smem[];
    const uint32_t sbase = s2u(smem);

    const int tid = threadIdx.x, wid = tid>>5, lane = tid&31;
    const int wm = wid & 3, wn = wid >> 2;
    const int nt = blockIdx.x, mt = blockIdx.y, z = blockIdx.z;

    const __half* A; const __half* B;
    size_t saz = 0, sbz = 0;
    if(MODE==0){ A = a_pk;  B = b_pk; }
    else if(MODE==1){ A = q_pk; B = k_pk; saz = (size_t)LR*8192; sbz = (size_t)LR*8192; }
    else if(MODE==2){ A = p_pk; B = vt_pk; saz = (size_t)LR*768; sbz = (size_t)NS*DHH*LR; }
    else { A = a_pk; B = wo_pk; }

    const int zz    = (MODE==1) ? (z>>2) : z;
    const int kbase = (MODE==1) ? (z&3)*KRL : 0;

    const __half* Ab = A + saz*zz + (size_t)(mt*128)*KPA;
    const __half* Bb = B + sbz*zz + (size_t)(nt*128)*KR;

    float acc[2][8][4];
    #pragma unroll
    for(int i=0;i<2;i++)
        #pragma unroll
        for(int j=0;j<8;j++)
            #pragma unroll
            for(int k=0;k<4;k++) acc[i][j][k]=0.f;

    auto issue_stage = [&](int c){
        const uint32_t stg = sbase + (uint32_t)(c % NSTAGE)*STG_BYTES;
        const int aoff = (c < H) ? (kbase + c*64) : (KR + kbase + (c-H)*64);
        const int boff = kbase + (c % H)*64;
        const __half* ac = Ab + aoff;
        const __half* bc = Bb + boff;
        #pragma unroll
        for(int t=0;t<4;t++){
            int idx = tid + t*256;
            int r = idx>>3, cc = idx&7;
            uint32_t sa = stg + r*144 + cc*16;
            const void* ga = ac + (size_t)r*KPA + cc*8;
            asm volatile("cp.async.cg.shared.global [%0], [%1], 16;"::"r"(sa),"l"(ga));
        }
        #pragma unroll
        for(int t=0;t<4;t++){
            int idx = tid + t*256;
            int r = idx>>3, cc = idx&7;
            uint32_t sb = stg + B_OFF_BYTES + r*144 + cc*16;
            const void* gb = bc + (size_t)r*KR + cc*8;
            asm volatile("cp.async.cg.shared.global [%0], [%1], 16;"::"r"(sb),"l"(gb));
        }
        asm volatile("cp.async.commit_group;");
    };

    issue_stage(0);
    if(Cn > 1) issue_stage(1);

    for(int c = 0; c < Cn; c++){
        if(c < Cn-1) asm volatile("cp.async.wait_group 1;");
        else         asm volatile("cp.async.wait_group 0;");
        __syncthreads();
        if(c+2 < Cn) issue_stage(c+2);

        const uint32_t stg = sbase + (uint32_t)(c % NSTAGE)*STG_BYTES;
        const uint32_t abase = stg;
        const uint32_t bbase = stg + B_OFF_BYTES;
        #pragma unroll
        for(int ks=0; ks<4; ks++){
            uint32_t ar[2][4];
            #pragma unroll
            for(int mi=0;mi<2;mi++){
                int row = wm*32 + mi*16 + (lane&15);
                uint32_t addr = abase + row*144 + ks*32 + (lane>>4)*16;
                asm volatile("ldmatrix.sync.aligned.m8n8.x4.shared.b16 {%0,%1,%2,%3}, [%4];"
                    : "=r"(ar[mi][0]),"=r"(ar[mi][1]),"=r"(ar[mi][2]),"=r"(ar[mi][3])
                    : "r"(addr));
            }
            uint32_t br[4][4];
            #pragma unroll
            for(int nb=0;nb<4;nb++){
                int nrow = wn*64 + nb*16 + (lane&7) + ((lane>>4)&1)*8;
                uint32_t addr = bbase + nrow*144 + ks*32 + ((lane>>3)&1)*16;
                asm volatile("ldmatrix.sync.aligned.m8n8.x4.shared.b16 {%0,%1,%2,%3}, [%4];"
                    : "=r"(br[nb][0]),"=r"(br[nb][1]),"=r"(br[nb][2]),"=r"(br[nb][3])
                    : "r"(addr));
            }
            #pragma unroll
            for(int mi=0;mi<2;mi++)
                #pragma unroll
                for(int ni=0;ni<8;ni++){
                    uint32_t b0 = br[ni>>1][(ni&1)*2];
                    uint32_t b1 = br[ni>>1][(ni&1)*2+1];
                    float* cc2 = acc[mi][ni];
                    asm volatile(
                        "mma.sync.aligned.m16n8k16.row.col.f32.f16.f16.f32 "
                        "{%0,%1,%2,%3}, {%4,%5,%6,%7}, {%8,%9}, {%0,%1,%2,%3};"
                        : "+f"(cc2[0]),"+f"(cc2[1]),"+f"(cc2[2]),"+f"(cc2[3])
                        : "r"(ar[mi][0]),"r"(ar[mi][1]),"r"(ar[mi][2]),"r"(ar[mi][3]),
                          "r"(b0),"r"(b1));
                }
        }
        __syncthreads();
    }

    const int grow = lane>>2, gcol = (lane&3)*2;

    if(MODE==1){
        #pragma unroll
        for(int mi=0;mi<2;mi++)
            #pragma unroll
            for(int ni=0;ni<8;ni++){
                int R0 = mt*128 + wm*32 + mi*16 + grow;
                int C0 = nt*128 + wn*64 + ni*8 + gcol;
                atomicAdd(&g_attn[zz*LL + R0*LR + C0],       acc[mi][ni][0]);
                atomicAdd(&g_attn[zz*LL + R0*LR + C0+1],     acc[mi][ni][1]);
                atomicAdd(&g_attn[zz*LL + (R0+8)*LR + C0],   acc[mi][ni][2]);
                atomicAdd(&g_attn[zz*LL + (R0+8)*LR + C0+1], acc[mi][ni][3]);
            }
        return;
    }
    if(MODE==3){
        #pragma unroll
        for(int mi=0;mi<2;mi++)
            #pragma unroll
            for(int ni=0;ni<8;ni++){
                int R0 = mt*128 + wm*32 + mi*16 + grow;
                int C0 = nt*128 + wn*64 + ni*8 + gcol;
                outp[R0*DM + C0]       = acc[mi][ni][0] + p0[C0];
                outp[R0*DM + C0+1]     = acc[mi][ni][1] + p0[C0+1];
                outp[(R0+8)*DM + C0]   = acc[mi][ni][2] + p0[C0];
                outp[(R0+8)*DM + C0+1] = acc[mi][ni][3] + p0[C0+1];
            }
        return;
    }

    // staged epilogue (MODE 0 / MODE 2): accumulators -> smem [128][129] fp32
    float* st = (float*)smem;
    #pragma unroll
    for(int mi=0;mi<2;mi++)
        #pragma unroll
        for(int ni=0;ni<8;ni++){
            int r = wm*32 + mi*16 + grow;
            int cc = wn*64 + ni*8 + gcol;
            st[r*129 + cc]       = acc[mi][ni][0];
            st[r*129 + cc+1]     = acc[mi][ni][1];
            st[(r+8)*129 + cc]   = acc[mi][ni][2];
            st[(r+8)*129 + cc+1] = acc[mi][ni][3];
        }
    __syncthreads();

    if(MODE==0){
        const int n  = (mt*128)/LR;
        const int l0 = (mt*128)%LR;
        const int cg0 = nt*128;
        const int matq = cg0>>8;
        const int cl0 = cg0&255;
        if(matq==2){
            // vt_pk: transposed column writes
            if(tid < 128){
                int cl = cl0 + tid;
                int h = cl>>5, d = cl&31;
                __half* dst = &vt_pk[((size_t)(h*NS*DHH) + n*DHH + d)*LR + l0];
                for(int l=0;l<128;l+=2){
                    __half2 hv = __floats2half2_rn(st[l*129+tid], st[(l+1)*129+tid]);
                    *(__half2*)&dst[l] = hv;
                }
            }
        } else {
            for(int seg = tid; seg < 512; seg += 256){
                int l = seg >> 2, hh = seg & 3;
                int cl = cl0 + hh*32;
                int h = cl>>5;
                const float* srow = &st[l*129 + hh*32];
                if(matq==0){
                    __half2* dst = (__half2*)&q_pk[((size_t)h*LR + l0+l)*8192 + n*DHH];
                    #pragma unroll
                    for(int d2=0; d2<16; d2++)
                        dst[d2] = __floats2half2_rn(srow[d2*2], srow[d2*2+1]);
                } else if(matq==1){
                    __half2* dst = (__half2*)&k_pk[((size_t)h*LR + l0+l)*8192 + n*DHH];
                    #pragma unroll
                    for(int d2=0; d2<16; d2++)
                        dst[d2] = __floats2half2_rn(srow[d2*2]*SCALE_DH, srow[d2*2+1]*SCALE_DH);
                } else if(matq==3){
                    float* dst = &g_gate[(size_t)(n*LR + l0+l)*HDM + cl];
                    #pragma unroll
                    for(int d=0; d<32; d++)
                        dst[d] = 1.f/(1.f + expf(-(srow[d] + p0[cl+d])));
                } else {
                    // seq logits: full dot32 owned by this thread
                    int lg = l0 + l;
                    const float* sq = &g_swq[lg*HDM + cl];
                    float pv = g_lbias[lg*NH + h];
                    #pragma unroll
                    for(int d=0; d<32; d++) pv += sq[d]*srow[d];
                    g_logit[(lg*NH + h)*NS + n] = pv;
                }
            }
        }
    } else {  // MODE 2: gate + pack into a_pk [hi|lo]
        for(int seg = tid; seg < 512; seg += 256){
            int q = seg>>2, ss = seg&3;
            int s = nt*4 + ss;
            size_t rr = (size_t)s*LR + mt*128 + q;
            const float* gr = &g_gate[rr*HDM + z*DHH];
            const float* srow = &st[q*129 + ss*32];
            __half* dst = &a_pk[rr*512 + z*DHH];
            #pragma unroll
            for(int d=0; d<32; d+=2){
                float v0 = srow[d]*gr[d], v1 = srow[d+1]*gr[d+1];
                __half h0, l0h, h1, l1h;
                hsplit(v0, h0, l0h); hsplit(v1, h1, l1h);
                *(__half2*)&dst[d]       = __halves2half2(h0, h1);
                *(__half2*)&dst[256 + d] = __halves2half2(l0h, l1h);
            }
        }
    }
}

// ---------------- 5. softmax over n + scale q_pk in place ----------------
__global__ void seq_softmax_kernel(){
    __shared__ float sh[8];
    __shared__ float wsh[NS];
    int l = blockIdx.x >> 3, h = blockIdx.x & 7;
    int tid = threadIdx.x;
    float x = g_logit[(l*NH+h)*NS + tid];
    float m = warpMax(x);
    if((tid&31)==0) sh[tid>>5]=m;
    __syncthreads();
    if(tid<32){ float mm=(tid<8)?sh[tid]:-1e30f; mm=warpMax(mm); if(tid==0) sh[0]=mm; }
    __syncthreads();
    m = sh[0];
    __syncthreads();
    float e = expf(x - m);
    float s = warpRed(e);
    if((tid&31)==0) sh[tid>>5]=s;
    __syncthreads();
    if(tid<32){ float ss=(tid<8)?sh[tid]:0.f; ss=warpRed(ss); if(tid==0) sh[0]=ss; }
    __syncthreads();
    s = sh[0];
    wsh[tid] = e / s;
    __syncthreads();
    __half2* qp = (__half2*)(q_pk + (size_t)(h*LR + l)*8192);
    for(int i=tid; i<4096; i+=256){
        float w = wsh[i>>4];
        float2 v = __half22float2(qp[i]);
        qp[i] = __floats2half2_rn(v.x*w, v.y*w);
    }
}

// ---------------- 6. bias = LN(pair) @ wb ----------------
__global__ void bias_kernel(const float* __restrict__ pair, const float* __restrict__ g,
                            const float* __restrict__ b, const float* __restrict__ wb){
    __shared__ float wbs[NH][DP];
    int tid = threadIdx.x;
    for(int idx=tid; idx<NH*DP; idx+=256){
        int h = idx / DP, k = idx % DP;
        wbs[h][k] = wb[k*NH + h];
    }
    __syncthreads();
    int warp = tid >> 5, lane = tid & 31;
    int p = blockIdx.x*8 + warp;
    float4 xv = ((const float4*)(pair + (size_t)p*DP))[lane];
    float sum = xv.x+xv.y+xv.z+xv.w;
    float sq  = xv.x*xv.x+xv.y*xv.y+xv.z*xv.z+xv.w*xv.w;
    sum = warpRed(sum); sq = warpRed(sq);
    float mean = sum*(1.f/DP);
    float var  = sq*(1.f/DP) - mean*mean;
    float inv  = rsqrtf(var + 1e-5f);
    float4 gv = ((const float4*)g)[lane];
    float4 bv = ((const float4*)b)[lane];
    float xn0 = (xv.x-mean)*inv*gv.x + bv.x;
    float xn1 = (xv.y-mean)*inv*gv.y + bv.y;
    float xn2 = (xv.z-mean)*inv*gv.z + bv.z;
    float xn3 = (xv.w-mean)*inv*gv.w + bv.w;
    #pragma unroll
    for(int h=0;h<NH;h++){
        float4 wv4 = ((const float4*)(wbs[h]))[lane];
        float prt = xn0*wv4.x + xn1*wv4.y + xn2*wv4.z + xn3*wv4.w;
        prt = warpRed(prt);
        if(lane==0) g_bias[h*LL + p] = prt;
    }
}

// ---------------- 8. softmax over k (+ bias) -> packed P [hi|lo] ----------------
__global__ void attn_softmax_kernel(){
    __shared__ float sh[4];
    int row = blockIdx.x;   // h*LR + q
    const float* a = g_attn + (size_t)row*LR;
    const float* bi = g_bias + (size_t)row*LR;
    int tid = threadIdx.x;  // 128 threads
    float x0 = a[tid]       + bi[tid];
    float x1 = a[tid+128]   + bi[tid+128];
    float x2 = a[tid+256]   + bi[tid+256];
    float m = fmaxf(x0, fmaxf(x1, x2));
    m = warpMax(m);
    if((tid&31)==0) sh[tid>>5]=m;
    __syncthreads();
    if(tid<32){ float mm=(tid<4)?sh[tid]:-1e30f; mm=warpMax(mm); if(tid==0) sh[0]=mm; }
    __syncthreads();
    m = sh[0];
    __syncthreads();
    x0 = expf(x0-m); x1 = expf(x1-m); x2 = expf(x2-m);
    float s = warpRed(x0+x1+x2);
    if((tid&31)==0) sh[tid>>5]=s;
    __syncthreads();
    if(tid<32){ float ss=(tid<4)?sh[tid]:0.f; ss=warpRed(ss); if(tid==0) sh[0]=ss; }
    __syncthreads();
    s = sh[0];
    float rcp = 1.f/s;
    __half* pp = p_pk + (size_t)row*768;
    __half hi, lo;
    hsplit(x0*rcp, hi, lo); pp[tid]     = hi; pp[tid+384]     = lo;
    hsplit(x1*rcp, hi, lo); pp[tid+128] = hi; pp[tid+128+384] = lo;
    hsplit(x2*rcp, hi, lo); pp[tid+256] = hi; pp[tid+256+384] = lo;
}

// ---------------- launch ----------------
extern "C" void kernel_launch(void* const* d_in, const int* in_sizes, int n_in,
                              void* d_out, int out_size){
    const float* msa       = (const float*)d_in[0];
    const float* pair      = (const float*)d_in[1];
    const float* ln_msa_g  = (const float*)d_in[2];
    const float* ln_msa_b  = (const float*)d_in[3];
    const float* ln_pair_g = (const float*)d_in[4];
    const float* ln_pair_b = (const float*)d_in[5];
    const float* sw_q_w    = (const float*)d_in[6];
    const float* sw_q_b    = (const float*)d_in[7];
    const float* sw_k_w    = (const float*)d_in[8];
    const float* sw_k_b    = (const float*)d_in[9];
    const float* wq        = (const float*)d_in[10];
    const float* wk        = (const float*)d_in[11];
    const float* wv        = (const float*)d_in[12];
    const float* wb        = (const float*)d_in[13];
    const float* wg        = (const float*)d_in[14];
    const float* bg        = (const float*)d_in[15];
    const float* wo        = (const float*)d_in[16];
    const float* bo        = (const float*)d_in[17];
    float* out = (float*)d_out;

    cudaFuncSetAttribute(gemm_mma<0>, cudaFuncAttributeMaxDynamicSharedMemorySize, GSMEM_BYTES);
    cudaFuncSetAttribute(gemm_mma<1>, cudaFuncAttributeMaxDynamicSharedMemorySize, GSMEM_BYTES);
    cudaFuncSetAttribute(gemm_mma<2>, cudaFuncAttributeMaxDynamicSharedMemorySize, GSMEM_BYTES);
    cudaFuncSetAttribute(gemm_mma<3>, cudaFuncAttributeMaxDynamicSharedMemorySize, GSMEM_BYTES);

    ln_msa_kernel<<<NL, 256>>>(msa, ln_msa_g, ln_msa_b);
    pack_w_kernel<<<1280, 256>>>(wq, wk, wv, wg, sw_k_w);
    pack_wo_kernel<<<256, 256>>>(wo);
    swq_kernel<<<LR, 256>>>(sw_q_w, sw_q_b);
    lbias_kernel<<<LR, 256>>>(sw_k_b);
    zero_attn_kernel<<<(NH*LL+1023)/1024, 1024>>>();

    // proj: [98304 x 1280], K=256 (no split), epilogue computes seq logits
    gemm_mma<0><<<dim3(10, 768, 1), 256, GSMEM_BYTES>>>(bg, nullptr, nullptr);

    seq_softmax_kernel<<<LR*NH, 256>>>();
    bias_kernel<<<LL/8, 256>>>(pair, ln_pair_g, ln_pair_b, wb);

    // qk: per head [384 x 384], K=8192 (no split), split-K x4 -> atomicAdd
    gemm_mma<1><<<dim3(3, 3, NH*4), 256, GSMEM_BYTES>>>(nullptr, nullptr, nullptr);

    attn_softmax_kernel<<<NH*LR, 128>>>();

    // av: per head [384 x 8192], K=384, A split [hi|lo]
    gemm_mma<2><<<dim3(64, 3, NH), 256, GSMEM_BYTES>>>(nullptr, nullptr, nullptr);

    // out: [98304 x 256], K=256, A split [hi|lo]
    gemm_mma<3><<<dim3(2, 768, 1), 256, GSMEM_BYTES>>>(bo, nullptr, out);
}

// round 9
// speedup vs baseline: 3.6742x; 1.2402x over previous
#include <cuda_runtime.h>
#include <cuda_fp16.h>
#include <math.h>
#include <stdint.h>

// Problem constants
#define NS 256
#define LR 384
#define DM 256
#define DP 128
#define NH 8
#define DHH 32
#define HDM 256
#define NL (NS*LR)      // 98304
#define LL (LR*LR)      // 147456
#define SCALE_DH 0.17677669529663687f

// ---------------- device scratch ----------------
__device__ float g_msan[LR*DM];           // only n=0 rows needed (swq)
__device__ float g_swq[LR*HDM];
__device__ float g_lbias[LR*NH];
__device__ __half g_gate[NL*HDM];
__device__ float g_logit[LR*NH*NS];
__device__ float g_bias[NH*LL];
__device__ float g_attn[NH*LL];           // qk logits (split-K atomics)

// packed fp16 operands (all single fp16 now; no hi|lo splits)
__device__ __half a_pk[(size_t)NL*256];            // [r][256]: msan (proj) / gated-out (out)
__device__ __half b_pk[1280*256];                  // proj weights^T, [n][256]
__device__ __half wo_pk[DM*256];                   // wo^T, [n][256]
__device__ __half q_pk[(size_t)NH*LR*8192];        // [h*384+l][n*32+d], raw then weighted
__device__ __half k_pk[(size_t)NH*LR*8192];        // [h*384+l][n*32+d]
__device__ __half vt_pk[(size_t)NH*NS*DHH*LR];     // [h*8192+(s*32+d)][l]
__device__ __half p_pk[(size_t)NH*LR*384];         // [h*384+q][k]

// ---------------- helpers ----------------
__device__ __forceinline__ float warpRed(float v){
    #pragma unroll
    for(int o=16;o>0;o>>=1) v += __shfl_xor_sync(0xffffffffu, v, o);
    return v;
}
__device__ __forceinline__ float warpMax(float v){
    #pragma unroll
    for(int o=16;o>0;o>>=1) v = fmaxf(v, __shfl_xor_sync(0xffffffffu, v, o));
    return v;
}
__device__ __forceinline__ uint32_t s2u(const void* p){
    uint32_t a; asm("{ .reg .u64 t; cvta.to.shared.u64 t, %1; cvt.u32.u64 %0, t; }" : "=r"(a) : "l"(p));
    return a;
}

// ---------------- 1. LayerNorm of msa + pack A ----------------
__global__ void ln_msa_kernel(const float* __restrict__ x,
                              const float* __restrict__ gg,
                              const float* __restrict__ bb){
    __shared__ float s1[8], s2[8];
    int row = blockIdx.x, tid = threadIdx.x;
    float v = x[row*DM + tid];
    float a = warpRed(v);
    float b = warpRed(v*v);
    if((tid&31)==0){ s1[tid>>5]=a; s2[tid>>5]=b; }
    __syncthreads();
    if(tid<32){
        float aa = (tid<8)? s1[tid] : 0.f;
        float bb2 = (tid<8)? s2[tid] : 0.f;
        aa = warpRed(aa); bb2 = warpRed(bb2);
        if(tid==0){ s1[0]=aa; s2[0]=bb2; }
    }
    __syncthreads();
    float mean = s1[0]*(1.f/DM);
    float var  = s2[0]*(1.f/DM) - mean*mean;
    float inv  = rsqrtf(var + 1e-5f);
    float y = (v-mean)*inv*gg[tid] + bb[tid];
    if(row < LR) g_msan[row*DM + tid] = y;    // only n=0 rows consumed downstream
    a_pk[(size_t)row*256 + tid] = __float2half(y);
}

// ---------------- 2. pack weights (transposed, single fp16) ----------------
__global__ void pack_w_kernel(const float* __restrict__ wq, const float* __restrict__ wk,
                              const float* __restrict__ wv, const float* __restrict__ wg,
                              const float* __restrict__ wsk, const float* __restrict__ wo){
    int n = blockIdx.x, k = threadIdx.x;
    if(n < 1280){
        int mat = n >> 8, nl = n & 255;
        const float* W = (mat==0)?wq:(mat==1)?wk:(mat==2)?wv:(mat==3)?wg:wsk;
        b_pk[n*256 + k] = __float2half(W[k*HDM + nl]);
    } else {
        int nl = n - 1280;
        wo_pk[nl*256 + k] = __float2half(wo[k*DM + nl]);
    }
}

// ---------------- 3. swq (+ fused lbias) ----------------
__global__ void swq_kernel(const float* __restrict__ W, const float* __restrict__ bqb,
                           const float* __restrict__ skb){
    __shared__ float t[DM];
    int l = blockIdx.x, tid = threadIdx.x, lane = tid&31;
    t[tid] = g_msan[l*DM + tid];
    __syncthreads();
    float acc = 0.f;
    #pragma unroll 8
    for(int k=0;k<DM;k++) acc += t[k]*W[k*HDM + tid];
    float val = (acc + bqb[tid]) * SCALE_DH;
    g_swq[l*HDM + tid] = val;
    float pv = val * skb[tid];
    pv = warpRed(pv);                       // warp = one head (32 consecutive cols)
    if(lane==0) g_lbias[l*NH + (tid>>5)] = pv;
}

// ---------------- zero g_attn ----------------
__global__ void zero_attn_kernel(){
    int i = blockIdx.x*1024 + threadIdx.x;
    if(i < NH*LL) g_attn[i] = 0.f;
}

// ---------------- mma.sync fp16 GEMM, 3-stage cp.async ----------------
// MODE 0: proj  A=a_pk[NL x 256],     B=b_pk[1280 x 256]   (staged epilogue + logits)
// MODE 1: qk    A=q_pk[h][384x8192],  B=k_pk[h][384x8192]  (split-K x4, atomicAdd)
// MODE 2: av    A=p_pk[h][384x384],   B=vt_pk[h][8192x384] (staged: gate + a_pk)
// MODE 3: out   A=a_pk[NL x 256],     B=wo_pk[256 x 256]   (direct)
#define STG_BYTES 36864                 // (128 A-rows + 128 B-rows) * 144B
#define B_OFF_BYTES 18432
#define NSTAGE 3
#define GSMEM_BYTES (NSTAGE*STG_BYTES)  // 110592

template<int MODE>
__global__ __launch_bounds__(256)
void gemm_mma(const float* __restrict__ p0, float* __restrict__ outp){
    constexpr int KR  = (MODE==1) ? 8192 : (MODE==2) ? 384 : 256;  // real K = pitch
    constexpr int KRL = (MODE==1) ? 2048 : KR;                      // per-CTA K
    constexpr int Cn  = KRL/64;

    extern __shared__ char smem[];
    const uint32_t sbase = s2u(smem);

    const int tid = threadIdx.x, wid = tid>>5, lane = tid&31;
    const int wm = wid & 3, wn = wid >> 2;
    const int nt = blockIdx.x, mt = blockIdx.y, z = blockIdx.z;

    const __half* A; const __half* B;
    size_t saz = 0, sbz = 0;
    if(MODE==0){ A = a_pk;  B = b_pk; }
    else if(MODE==1){ A = q_pk; B = k_pk; saz = (size_t)LR*8192; sbz = (size_t)LR*8192; }
    else if(MODE==2){ A = p_pk; B = vt_pk; saz = (size_t)LR*384; sbz = (size_t)NS*DHH*LR; }
    else { A = a_pk; B = wo_pk; }

    const int zz    = (MODE==1) ? (z>>2) : z;
    const int kbase = (MODE==1) ? (z&3)*KRL : 0;

    const __half* Ab = A + saz*zz + (size_t)(mt*128)*KR;
    const __half* Bb = B + sbz*zz + (size_t)(nt*128)*KR;

    float acc[2][8][4];
    #pragma unroll
    for(int i=0;i<2;i++)
        #pragma unroll
        for(int j=0;j<8;j++)
            #pragma unroll
            for(int k=0;k<4;k++) acc[i][j][k]=0.f;

    auto issue_stage = [&](int c){
        const uint32_t stg = sbase + (uint32_t)(c % NSTAGE)*STG_BYTES;
        const int off = kbase + c*64;
        const __half* ac = Ab + off;
        const __half* bc = Bb + off;
        #pragma unroll
        for(int t=0;t<4;t++){
            int idx = tid + t*256;
            int r = idx>>3, cc = idx&7;
            uint32_t sa = stg + r*144 + cc*16;
            const void* ga = ac + (size_t)r*KR + cc*8;
            asm volatile("cp.async.cg.shared.global [%0], [%1], 16;"::"r"(sa),"l"(ga));
        }
        #pragma unroll
        for(int t=0;t<4;t++){
            int idx = tid + t*256;
            int r = idx>>3, cc = idx&7;
            uint32_t sb = stg + B_OFF_BYTES + r*144 + cc*16;
            const void* gb = bc + (size_t)r*KR + cc*8;
            asm volatile("cp.async.cg.shared.global [%0], [%1], 16;"::"r"(sb),"l"(gb));
        }
        asm volatile("cp.async.commit_group;");
    };

    issue_stage(0);
    if(Cn > 1) issue_stage(1);

    for(int c = 0; c < Cn; c++){
        if(c < Cn-1) asm volatile("cp.async.wait_group 1;");
        else         asm volatile("cp.async.wait_group 0;");
        __syncthreads();
        if(c+2 < Cn) issue_stage(c+2);

        const uint32_t stg = sbase + (uint32_t)(c % NSTAGE)*STG_BYTES;
        const uint32_t abase = stg;
        const uint32_t bbase = stg + B_OFF_BYTES;
        #pragma unroll
        for(int ks=0; ks<4; ks++){
            uint32_t ar[2][4];
            #pragma unroll
            for(int mi=0;mi<2;mi++){
                int row = wm*32 + mi*16 + (lane&15);
                uint32_t addr = abase + row*144 + ks*32 + (lane>>4)*16;
                asm volatile("ldmatrix.sync.aligned.m8n8.x4.shared.b16 {%0,%1,%2,%3}, [%4];"
                    : "=r"(ar[mi][0]),"=r"(ar[mi][1]),"=r"(ar[mi][2]),"=r"(ar[mi][3])
                    : "r"(addr));
            }
            uint32_t br[4][4];
            #pragma unroll
            for(int nb=0;nb<4;nb++){
                int nrow = wn*64 + nb*16 + (lane&7) + ((lane>>4)&1)*8;
                uint32_t addr = bbase + nrow*144 + ks*32 + ((lane>>3)&1)*16;
                asm volatile("ldmatrix.sync.aligned.m8n8.x4.shared.b16 {%0,%1,%2,%3}, [%4];"
                    : "=r"(br[nb][0]),"=r"(br[nb][1]),"=r"(br[nb][2]),"=r"(br[nb][3])
                    : "r"(addr));
            }
            #pragma unroll
            for(int mi=0;mi<2;mi++)
                #pragma unroll
                for(int ni=0;ni<8;ni++){
                    uint32_t b0 = br[ni>>1][(ni&1)*2];
                    uint32_t b1 = br[ni>>1][(ni&1)*2+1];
                    float* cc2 = acc[mi][ni];
                    asm volatile(
                        "mma.sync.aligned.m16n8k16.row.col.f32.f16.f16.f32 "
                        "{%0,%1,%2,%3}, {%4,%5,%6,%7}, {%8,%9}, {%0,%1,%2,%3};"
                        : "+f"(cc2[0]),"+f"(cc2[1]),"+f"(cc2[2]),"+f"(cc2[3])
                        : "r"(ar[mi][0]),"r"(ar[mi][1]),"r"(ar[mi][2]),"r"(ar[mi][3]),
                          "r"(b0),"r"(b1));
                }
        }
        __syncthreads();
    }

    const int grow = lane>>2, gcol = (lane&3)*2;

    if(MODE==1){
        #pragma unroll
        for(int mi=0;mi<2;mi++)
            #pragma unroll
            for(int ni=0;ni<8;ni++){
                int R0 = mt*128 + wm*32 + mi*16 + grow;
                int C0 = nt*128 + wn*64 + ni*8 + gcol;
                atomicAdd(&g_attn[zz*LL + R0*LR + C0],       acc[mi][ni][0]);
                atomicAdd(&g_attn[zz*LL + R0*LR + C0+1],     acc[mi][ni][1]);
                atomicAdd(&g_attn[zz*LL + (R0+8)*LR + C0],   acc[mi][ni][2]);
                atomicAdd(&g_attn[zz*LL + (R0+8)*LR + C0+1], acc[mi][ni][3]);
            }
        return;
    }
    if(MODE==3){
        #pragma unroll
        for(int mi=0;mi<2;mi++)
            #pragma unroll
            for(int ni=0;ni<8;ni++){
                int R0 = mt*128 + wm*32 + mi*16 + grow;
                int C0 = nt*128 + wn*64 + ni*8 + gcol;
                outp[R0*DM + C0]       = acc[mi][ni][0] + p0[C0];
                outp[R0*DM + C0+1]     = acc[mi][ni][1] + p0[C0+1];
                outp[(R0+8)*DM + C0]   = acc[mi][ni][2] + p0[C0];
                outp[(R0+8)*DM + C0+1] = acc[mi][ni][3] + p0[C0+1];
            }
        return;
    }

    // staged epilogue (MODE 0 / MODE 2): accumulators -> smem [128][129] fp32
    float* st = (float*)smem;
    #pragma unroll
    for(int mi=0;mi<2;mi++)
        #pragma unroll
        for(int ni=0;ni<8;ni++){
            int r = wm*32 + mi*16 + grow;
            int cc = wn*64 + ni*8 + gcol;
            st[r*129 + cc]       = acc[mi][ni][0];
            st[r*129 + cc+1]     = acc[mi][ni][1];
            st[(r+8)*129 + cc]   = acc[mi][ni][2];
            st[(r+8)*129 + cc+1] = acc[mi][ni][3];
        }
    __syncthreads();

    if(MODE==0){
        const int n  = (mt*128)/LR;
        const int l0 = (mt*128)%LR;
        const int cg0 = nt*128;
        const int matq = cg0>>8;
        const int cl0 = cg0&255;
        if(matq==2){
            // vt_pk: transposed column writes
            if(tid < 128){
                int cl = cl0 + tid;
                int h = cl>>5, d = cl&31;
                __half* dst = &vt_pk[((size_t)(h*NS*DHH) + n*DHH + d)*LR + l0];
                for(int l=0;l<128;l+=2){
                    __half2 hv = __floats2half2_rn(st[l*129+tid], st[(l+1)*129+tid]);
                    *(__half2*)&dst[l] = hv;
                }
            }
        } else {
            for(int seg = tid; seg < 512; seg += 256){
                int l = seg >> 2, hh = seg & 3;
                int cl = cl0 + hh*32;
                int h = cl>>5;
                const float* srow = &st[l*129 + hh*32];
                if(matq==0){
                    __half2* dst = (__half2*)&q_pk[((size_t)h*LR + l0+l)*8192 + n*DHH];
                    #pragma unroll
                    for(int d2=0; d2<16; d2++)
                        dst[d2] = __floats2half2_rn(srow[d2*2], srow[d2*2+1]);
                } else if(matq==1){
                    __half2* dst = (__half2*)&k_pk[((size_t)h*LR + l0+l)*8192 + n*DHH];
                    #pragma unroll
                    for(int d2=0; d2<16; d2++)
                        dst[d2] = __floats2half2_rn(srow[d2*2]*SCALE_DH, srow[d2*2+1]*SCALE_DH);
                } else if(matq==3){
                    __half2* dst = (__half2*)&g_gate[(size_t)(n*LR + l0+l)*HDM + cl];
                    #pragma unroll
                    for(int d2=0; d2<16; d2++){
                        float v0 = 1.f/(1.f + expf(-(srow[d2*2]   + p0[cl+d2*2])));
                        float v1 = 1.f/(1.f + expf(-(srow[d2*2+1] + p0[cl+d2*2+1])));
                        dst[d2] = __floats2half2_rn(v0, v1);
                    }
                } else {
                    // seq logits: full dot32 owned by this thread
                    int lg = l0 + l;
                    const float* sq = &g_swq[lg*HDM + cl];
                    float pv = g_lbias[lg*NH + h];
                    #pragma unroll
                    for(int d=0; d<32; d++) pv += sq[d]*srow[d];
                    g_logit[(lg*NH + h)*NS + n] = pv;
                }
            }
        }
    } else {  // MODE 2: gate + pack into a_pk
        for(int seg = tid; seg < 512; seg += 256){
            int q = seg>>2, ss = seg&3;
            int s = nt*4 + ss;
            size_t rr = (size_t)s*LR + mt*128 + q;
            const __half2* gr = (const __half2*)&g_gate[rr*HDM + z*DHH];
            const float* srow = &st[q*129 + ss*32];
            __half2* dst = (__half2*)&a_pk[rr*256 + z*DHH];
            #pragma unroll
            for(int d2=0; d2<16; d2++){
                float2 g2 = __half22float2(gr[d2]);
                dst[d2] = __floats2half2_rn(srow[d2*2]*g2.x, srow[d2*2+1]*g2.y);
            }
        }
    }
}

// ---------------- 5. softmax over n + scale q_pk in place ----------------
__global__ void seq_softmax_kernel(){
    __shared__ float sh[8];
    __shared__ float wsh[NS];
    int l = blockIdx.x >> 3, h = blockIdx.x & 7;
    int tid = threadIdx.x;
    float x = g_logit[(l*NH+h)*NS + tid];
    float m = warpMax(x);
    if((tid&31)==0) sh[tid>>5]=m;
    __syncthreads();
    if(tid<32){ float mm=(tid<8)?sh[tid]:-1e30f; mm=warpMax(mm); if(tid==0) sh[0]=mm; }
    __syncthreads();
    m = sh[0];
    __syncthreads();
    float e = expf(x - m);
    float s = warpRed(e);
    if((tid&31)==0) sh[tid>>5]=s;
    __syncthreads();
    if(tid<32){ float ss=(tid<8)?sh[tid]:0.f; ss=warpRed(ss); if(tid==0) sh[0]=ss; }
    __syncthreads();
    s = sh[0];
    wsh[tid] = e / s;
    __syncthreads();
    __half2* qp = (__half2*)(q_pk + (size_t)(h*LR + l)*8192);
    for(int i=tid; i<4096; i+=256){
        float w = wsh[i>>4];
        float2 v = __half22float2(qp[i]);
        qp[i] = __floats2half2_rn(v.x*w, v.y*w);
    }
}

// ---------------- 6. bias = LN(pair) @ wb ----------------
__global__ void bias_kernel(const float* __restrict__ pair, const float* __restrict__ g,
                            const float* __restrict__ b, const float* __restrict__ wb){
    __shared__ float wbs[NH][DP];
    int tid = threadIdx.x;
    for(int idx=tid; idx<NH*DP; idx+=256){
        int h = idx / DP, k = idx % DP;
        wbs[h][k] = wb[k*NH + h];
    }
    __syncthreads();
    int warp = tid >> 5, lane = tid & 31;
    int p = blockIdx.x*8 + warp;
    float4 xv = ((const float4*)(pair + (size_t)p*DP))[lane];
    float sum = xv.x+xv.y+xv.z+xv.w;
    float sq  = xv.x*xv.x+xv.y*xv.y+xv.z*xv.z+xv.w*xv.w;
    sum = warpRed(sum); sq = warpRed(sq);
    float mean = sum*(1.f/DP);
    float var  = sq*(1.f/DP) - mean*mean;
    float inv  = rsqrtf(var + 1e-5f);
    float4 gv = ((const float4*)g)[lane];
    float4 bv = ((const float4*)b)[lane];
    float xn0 = (xv.x-mean)*inv*gv.x + bv.x;
    float xn1 = (xv.y-mean)*inv*gv.y + bv.y;
    float xn2 = (xv.z-mean)*inv*gv.z + bv.z;
    float xn3 = (xv.w-mean)*inv*gv.w + bv.w;
    #pragma unroll
    for(int h=0;h<NH;h++){
        float4 wv4 = ((const float4*)(wbs[h]))[lane];
        float prt = xn0*wv4.x + xn1*wv4.y + xn2*wv4.z + xn3*wv4.w;
        prt = warpRed(prt);
        if(lane==0) g_bias[h*LL + p] = prt;
    }
}

// ---------------- 8. softmax over k (+ bias) -> p_pk fp16 ----------------
__global__ void attn_softmax_kernel(){
    __shared__ float sh[4];
    int row = blockIdx.x;   // h*LR + q
    const float* a = g_attn + (size_t)row*LR;
    const float* bi = g_bias + (size_t)row*LR;
    int tid = threadIdx.x;  // 128 threads
    float x0 = a[tid]       + bi[tid];
    float x1 = a[tid+128]   + bi[tid+128];
    float x2 = a[tid+256]   + bi[tid+256];
    float m = fmaxf(x0, fmaxf(x1, x2));
    m = warpMax(m);
    if((tid&31)==0) sh[tid>>5]=m;
    __syncthreads();
    if(tid<32){ float mm=(tid<4)?sh[tid]:-1e30f; mm=warpMax(mm); if(tid==0) sh[0]=mm; }
    __syncthreads();
    m = sh[0];
    __syncthreads();
    x0 = expf(x0-m); x1 = expf(x1-m); x2 = expf(x2-m);
    float s = warpRed(x0+x1+x2);
    if((tid&31)==0) sh[tid>>5]=s;
    __syncthreads();
    if(tid<32){ float ss=(tid<4)?sh[tid]:0.f; ss=warpRed(ss); if(tid==0) sh[0]=ss; }
    __syncthreads();
    s = sh[0];
    float rcp = 1.f/s;
    __half* pp = p_pk + (size_t)row*384;
    pp[tid]     = __float2half(x0*rcp);
    pp[tid+128] = __float2half(x1*rcp);
    pp[tid+256] = __float2half(x2*rcp);
}

// ---------------- launch ----------------
extern "C" void kernel_launch(void* const* d_in, const int* in_sizes, int n_in,
                              void* d_out, int out_size){
    const float* msa       = (const float*)d_in[0];
    const float* pair      = (const float*)d_in[1];
    const float* ln_msa_g  = (const float*)d_in[2];
    const float* ln_msa_b  = (const float*)d_in[3];
    const float* ln_pair_g = (const float*)d_in[4];
    const float* ln_pair_b = (const float*)d_in[5];
    const float* sw_q_w    = (const float*)d_in[6];
    const float* sw_q_b    = (const float*)d_in[7];
    const float* sw_k_w    = (const float*)d_in[8];
    const float* sw_k_b    = (const float*)d_in[9];
    const float* wq        = (const float*)d_in[10];
    const float* wk        = (const float*)d_in[11];
    const float* wv        = (const float*)d_in[12];
    const float* wb        = (const float*)d_in[13];
    const float* wg        = (const float*)d_in[14];
    const float* bg        = (const float*)d_in[15];
    const float* wo        = (const float*)d_in[16];
    const float* bo        = (const float*)d_in[17];
    float* out = (float*)d_out;

    cudaFuncSetAttribute(gemm_mma<0>, cudaFuncAttributeMaxDynamicSharedMemorySize, GSMEM_BYTES);
    cudaFuncSetAttribute(gemm_mma<1>, cudaFuncAttributeMaxDynamicSharedMemorySize, GSMEM_BYTES);
    cudaFuncSetAttribute(gemm_mma<2>, cudaFuncAttributeMaxDynamicSharedMemorySize, GSMEM_BYTES);
    cudaFuncSetAttribute(gemm_mma<3>, cudaFuncAttributeMaxDynamicSharedMemorySize, GSMEM_BYTES);

    ln_msa_kernel<<<NL, 256>>>(msa, ln_msa_g, ln_msa_b);
    pack_w_kernel<<<1536, 256>>>(wq, wk, wv, wg, sw_k_w, wo);
    swq_kernel<<<LR, 256>>>(sw_q_w, sw_q_b, sw_k_b);
    zero_attn_kernel<<<(NH*LL+1023)/1024, 1024>>>();

    // proj: [98304 x 1280], K=256
    gemm_mma<0><<<dim3(10, 768, 1), 256, GSMEM_BYTES>>>(bg, nullptr);

    seq_softmax_kernel<<<LR*NH, 256>>>();
    bias_kernel<<<LL/8, 256>>>(pair, ln_pair_g, ln_pair_b, wb);

    // qk: per head [384 x 384], K=8192, split-K x4 -> atomicAdd
    gemm_mma<1><<<dim3(3, 3, NH*4), 256, GSMEM_BYTES>>>(nullptr, nullptr);

    attn_softmax_kernel<<<NH*LR, 128>>>();

    // av: per head [384 x 8192], K=384
    gemm_mma<2><<<dim3(64, 3, NH), 256, GSMEM_BYTES>>>(nullptr, nullptr);

    // out: [98304 x 256], K=256
    gemm_mma<3><<<dim3(2, 768, 1), 256, GSMEM_BYTES>>>(bo, out);
}

// round 10
// speedup vs baseline: 3.7410x; 1.0182x over previous
#include <cuda_runtime.h>
#include <cuda_fp16.h>
#include <math.h>
#include <stdint.h>

// Problem constants
#define NS 256
#define LR 384
#define DM 256
#define DP 128
#define NH 8
#define DHH 32
#define HDM 256
#define NL (NS*LR)      // 98304
#define LL (LR*LR)      // 147456
#define SCALE_DH 0.17677669529663687f

// ---------------- device scratch ----------------
__device__ float g_msan[LR*DM];           // only n=0 rows needed (swq)
__device__ float g_swq[LR*HDM];
__device__ float g_lbias[LR*NH];
__device__ __half g_gate[NL*HDM];
__device__ float g_logit[LR*NH*NS];
__device__ float g_attn[NH*LL];           // pair bias, then += qk logits (split-K atomics)

// packed fp16 operands
__device__ __half a_pk[(size_t)NL*256];            // [r][256]: msan (proj) / gated-out (out)
__device__ __half b_pk[1280*256];                  // proj weights^T, [n][256]
__device__ __half wo_pk[DM*256];                   // wo^T, [n][256]
__device__ __half q_pk[(size_t)NH*LR*8192];        // [h*384+l][n*32+d], raw then weighted
__device__ __half k_pk[(size_t)NH*LR*8192];        // [h*384+l][n*32+d]
__device__ __half vt_pk[(size_t)NH*NS*DHH*LR];     // [h*8192+(s*32+d)][l]
__device__ __half p_pk[(size_t)NH*LR*384];         // [h*384+q][k]

// ---------------- helpers ----------------
__device__ __forceinline__ float warpRed(float v){
    #pragma unroll
    for(int o=16;o>0;o>>=1) v += __shfl_xor_sync(0xffffffffu, v, o);
    return v;
}
__device__ __forceinline__ float warpMax(float v){
    #pragma unroll
    for(int o=16;o>0;o>>=1) v = fmaxf(v, __shfl_xor_sync(0xffffffffu, v, o));
    return v;
}
__device__ __forceinline__ uint32_t s2u(const void* p){
    uint32_t a; asm("{ .reg .u64 t; cvta.to.shared.u64 t, %1; cvt.u32.u64 %0, t; }" : "=r"(a) : "l"(p));
    return a;
}

// ---------------- 1. LayerNorm of msa + pack A ----------------
__global__ void ln_msa_kernel(const float* __restrict__ x,
                              const float* __restrict__ gg,
                              const float* __restrict__ bb){
    __shared__ float s1[8], s2[8];
    int row = blockIdx.x, tid = threadIdx.x;
    float v = x[row*DM + tid];
    float a = warpRed(v);
    float b = warpRed(v*v);
    if((tid&31)==0){ s1[tid>>5]=a; s2[tid>>5]=b; }
    __syncthreads();
    if(tid<32){
        float aa = (tid<8)? s1[tid] : 0.f;
        float bb2 = (tid<8)? s2[tid] : 0.f;
        aa = warpRed(aa); bb2 = warpRed(bb2);
        if(tid==0){ s1[0]=aa; s2[0]=bb2; }
    }
    __syncthreads();
    float mean = s1[0]*(1.f/DM);
    float var  = s2[0]*(1.f/DM) - mean*mean;
    float inv  = rsqrtf(var + 1e-5f);
    float y = (v-mean)*inv*gg[tid] + bb[tid];
    if(row < LR) g_msan[row*DM + tid] = y;
    a_pk[(size_t)row*256 + tid] = __float2half(y);
}

// ---------------- 2. pack weights (transposed, single fp16) ----------------
__global__ void pack_w_kernel(const float* __restrict__ wq, const float* __restrict__ wk,
                              const float* __restrict__ wv, const float* __restrict__ wg,
                              const float* __restrict__ wsk, const float* __restrict__ wo){
    int n = blockIdx.x, k = threadIdx.x;
    if(n < 1280){
        int mat = n >> 8, nl = n & 255;
        const float* W = (mat==0)?wq:(mat==1)?wk:(mat==2)?wv:(mat==3)?wg:wsk;
        b_pk[n*256 + k] = __float2half(W[k*HDM + nl]);
    } else {
        int nl = n - 1280;
        wo_pk[nl*256 + k] = __float2half(wo[k*DM + nl]);
    }
}

// ---------------- 3. swq (+ fused lbias) ----------------
__global__ void swq_kernel(const float* __restrict__ W, const float* __restrict__ bqb,
                           const float* __restrict__ skb){
    __shared__ float t[DM];
    int l = blockIdx.x, tid = threadIdx.x, lane = tid&31;
    t[tid] = g_msan[l*DM + tid];
    __syncthreads();
    float acc = 0.f;
    #pragma unroll 8
    for(int k=0;k<DM;k++) acc += t[k]*W[k*HDM + tid];
    float val = (acc + bqb[tid]) * SCALE_DH;
    g_swq[l*HDM + tid] = val;
    float pv = val * skb[tid];
    pv = warpRed(pv);
    if(lane==0) g_lbias[l*NH + (tid>>5)] = pv;
}

// ---------------- mma.sync fp16 GEMM: BM=BN=128, 4 warps x (64x64), 3-stage cp.async ----------------
// MODE 0: proj  A=a_pk[NL x 256],     B=b_pk[1280 x 256]   (staged epilogue + logits)
// MODE 1: qk    A=q_pk[h][384x8192],  B=k_pk[h][384x8192]  (split-K x4, atomicAdd onto bias)
// MODE 2: av    A=p_pk[h][384x384],   B=vt_pk[h][8192x384] (staged: gate + a_pk)
// MODE 3: out   A=a_pk[NL x 256],     B=wo_pk[256 x 256]   (direct)
#define STG_BYTES 36864                 // (128 A-rows + 128 B-rows) * 144B
#define B_OFF_BYTES 18432
#define NSTAGE 3
#define GSMEM_BYTES (NSTAGE*STG_BYTES)  // 110592

template<int MODE>
__global__ __launch_bounds__(128)
void gemm_mma(const float* __restrict__ p0, float* __restrict__ outp){
    constexpr int KR  = (MODE==1) ? 8192 : (MODE==2) ? 384 : 256;  // real K = pitch
    constexpr int KRL = (MODE==1) ? 2048 : KR;                      // per-CTA K
    constexpr int Cn  = KRL/64;

    extern __shared__ char smem[];
    const uint32_t sbase = s2u(smem);

    const int tid = threadIdx.x, wid = tid>>5, lane = tid&31;
    const int wm = wid & 1, wn = wid >> 1;        // 2x2 warps of 64x64
    const int nt = blockIdx.x, mt = blockIdx.y, z = blockIdx.z;

    const __half* A; const __half* B;
    size_t saz = 0, sbz = 0;
    if(MODE==0){ A = a_pk;  B = b_pk; }
    else if(MODE==1){ A = q_pk; B = k_pk; saz = (size_t)LR*8192; sbz = (size_t)LR*8192; }
    else if(MODE==2){ A = p_pk; B = vt_pk; saz = (size_t)LR*384; sbz = (size_t)NS*DHH*LR; }
    else { A = a_pk; B = wo_pk; }

    const int zz    = (MODE==1) ? (z>>2) : z;
    const int kbase = (MODE==1) ? (z&3)*KRL : 0;

    const __half* Ab = A + saz*zz + (size_t)(mt*128)*KR;
    const __half* Bb = B + sbz*zz + (size_t)(nt*128)*KR;

    float acc[4][8][4];
    #pragma unroll
    for(int i=0;i<4;i++)
        #pragma unroll
        for(int j=0;j<8;j++)
            #pragma unroll
            for(int k=0;k<4;k++) acc[i][j][k]=0.f;

    auto issue_stage = [&](int c){
        const uint32_t stg = sbase + (uint32_t)(c % NSTAGE)*STG_BYTES;
        const int off = kbase + c*64;
        const __half* ac = Ab + off;
        const __half* bc = Bb + off;
        #pragma unroll
        for(int t=0;t<8;t++){
            int idx = tid + t*128;
            int r = idx>>3, cc = idx&7;
            uint32_t sa = stg + r*144 + cc*16;
            const void* ga = ac + (size_t)r*KR + cc*8;
            asm volatile("cp.async.cg.shared.global [%0], [%1], 16;"::"r"(sa),"l"(ga));
        }
        #pragma unroll
        for(int t=0;t<8;t++){
            int idx = tid + t*128;
            int r = idx>>3, cc = idx&7;
            uint32_t sb = stg + B_OFF_BYTES + r*144 + cc*16;
            const void* gb = bc + (size_t)r*KR + cc*8;
            asm volatile("cp.async.cg.shared.global [%0], [%1], 16;"::"r"(sb),"l"(gb));
        }
        asm volatile("cp.async.commit_group;");
    };

    issue_stage(0);
    if(Cn > 1) issue_stage(1);

    for(int c = 0; c < Cn; c++){
        if(c < Cn-1) asm volatile("cp.async.wait_group 1;");
        else         asm volatile("cp.async.wait_group 0;");
        __syncthreads();
        if(c+2 < Cn) issue_stage(c+2);

        const uint32_t stg = sbase + (uint32_t)(c % NSTAGE)*STG_BYTES;
        const uint32_t abase = stg;
        const uint32_t bbase = stg + B_OFF_BYTES;
        #pragma unroll
        for(int ks=0; ks<4; ks++){
            uint32_t ar[4][4];
            #pragma unroll
            for(int mi=0;mi<4;mi++){
                int row = wm*64 + mi*16 + (lane&15);
                uint32_t addr = abase + row*144 + ks*32 + (lane>>4)*16;
                asm volatile("ldmatrix.sync.aligned.m8n8.x4.shared.b16 {%0,%1,%2,%3}, [%4];"
                    : "=r"(ar[mi][0]),"=r"(ar[mi][1]),"=r"(ar[mi][2]),"=r"(ar[mi][3])
                    : "r"(addr));
            }
            uint32_t br[4][4];
            #pragma unroll
            for(int nb=0;nb<4;nb++){
                int nrow = wn*64 + nb*16 + (lane&7) + ((lane>>4)&1)*8;
                uint32_t addr = bbase + nrow*144 + ks*32 + ((lane>>3)&1)*16;
                asm volatile("ldmatrix.sync.aligned.m8n8.x4.shared.b16 {%0,%1,%2,%3}, [%4];"
                    : "=r"(br[nb][0]),"=r"(br[nb][1]),"=r"(br[nb][2]),"=r"(br[nb][3])
                    : "r"(addr));
            }
            #pragma unroll
            for(int mi=0;mi<4;mi++)
                #pragma unroll
                for(int ni=0;ni<8;ni++){
                    uint32_t b0 = br[ni>>1][(ni&1)*2];
                    uint32_t b1 = br[ni>>1][(ni&1)*2+1];
                    float* cc2 = acc[mi][ni];
                    asm volatile(
                        "mma.sync.aligned.m16n8k16.row.col.f32.f16.f16.f32 "
                        "{%0,%1,%2,%3}, {%4,%5,%6,%7}, {%8,%9}, {%0,%1,%2,%3};"
                        : "+f"(cc2[0]),"+f"(cc2[1]),"+f"(cc2[2]),"+f"(cc2[3])
                        : "r"(ar[mi][0]),"r"(ar[mi][1]),"r"(ar[mi][2]),"r"(ar[mi][3]),
                          "r"(b0),"r"(b1));
                }
        }
        __syncthreads();
    }

    const int grow = lane>>2, gcol = (lane&3)*2;

    if(MODE==1){
        #pragma unroll
        for(int mi=0;mi<4;mi++)
            #pragma unroll
            for(int ni=0;ni<8;ni++){
                int R0 = mt*128 + wm*64 + mi*16 + grow;
                int C0 = nt*128 + wn*64 + ni*8 + gcol;
                atomicAdd(&g_attn[zz*LL + R0*LR + C0],       acc[mi][ni][0]);
                atomicAdd(&g_attn[zz*LL + R0*LR + C0+1],     acc[mi][ni][1]);
                atomicAdd(&g_attn[zz*LL + (R0+8)*LR + C0],   acc[mi][ni][2]);
                atomicAdd(&g_attn[zz*LL + (R0+8)*LR + C0+1], acc[mi][ni][3]);
            }
        return;
    }
    if(MODE==3){
        #pragma unroll
        for(int mi=0;mi<4;mi++)
            #pragma unroll
            for(int ni=0;ni<8;ni++){
                int R0 = mt*128 + wm*64 + mi*16 + grow;
                int C0 = nt*128 + wn*64 + ni*8 + gcol;
                outp[R0*DM + C0]       = acc[mi][ni][0] + p0[C0];
                outp[R0*DM + C0+1]     = acc[mi][ni][1] + p0[C0+1];
                outp[(R0+8)*DM + C0]   = acc[mi][ni][2] + p0[C0];
                outp[(R0+8)*DM + C0+1] = acc[mi][ni][3] + p0[C0+1];
            }
        return;
    }

    // staged epilogue (MODE 0 / MODE 2): accumulators -> smem [128][129] fp32
    float* st = (float*)smem;
    #pragma unroll
    for(int mi=0;mi<4;mi++)
        #pragma unroll
        for(int ni=0;ni<8;ni++){
            int r = wm*64 + mi*16 + grow;
            int cc = wn*64 + ni*8 + gcol;
            st[r*129 + cc]       = acc[mi][ni][0];
            st[r*129 + cc+1]     = acc[mi][ni][1];
            st[(r+8)*129 + cc]   = acc[mi][ni][2];
            st[(r+8)*129 + cc+1] = acc[mi][ni][3];
        }
    __syncthreads();

    if(MODE==0){
        const int n  = (mt*128)/LR;
        const int l0 = (mt*128)%LR;
        const int cg0 = nt*128;
        const int matq = cg0>>8;
        const int cl0 = cg0&255;
        if(matq==2){
            // vt_pk: transposed column writes (128 threads, one col each)
            int cl = cl0 + tid;
            int h = cl>>5, d = cl&31;
            __half* dst = &vt_pk[((size_t)(h*NS*DHH) + n*DHH + d)*LR + l0];
            for(int l=0;l<128;l+=2){
                __half2 hv = __floats2half2_rn(st[l*129+tid], st[(l+1)*129+tid]);
                *(__half2*)&dst[l] = hv;
            }
        } else {
            for(int seg = tid; seg < 512; seg += 128){
                int l = seg >> 2, hh = seg & 3;
                int cl = cl0 + hh*32;
                int h = cl>>5;
                const float* srow = &st[l*129 + hh*32];
                if(matq==0){
                    __half2* dst = (__half2*)&q_pk[((size_t)h*LR + l0+l)*8192 + n*DHH];
                    #pragma unroll
                    for(int d2=0; d2<16; d2++)
                        dst[d2] = __floats2half2_rn(srow[d2*2], srow[d2*2+1]);
                } else if(matq==1){
                    __half2* dst = (__half2*)&k_pk[((size_t)h*LR + l0+l)*8192 + n*DHH];
                    #pragma unroll
                    for(int d2=0; d2<16; d2++)
                        dst[d2] = __floats2half2_rn(srow[d2*2]*SCALE_DH, srow[d2*2+1]*SCALE_DH);
                } else if(matq==3){
                    __half2* dst = (__half2*)&g_gate[(size_t)(n*LR + l0+l)*HDM + cl];
                    #pragma unroll
                    for(int d2=0; d2<16; d2++){
                        float v0 = 1.f/(1.f + expf(-(srow[d2*2]   + p0[cl+d2*2])));
                        float v1 = 1.f/(1.f + expf(-(srow[d2*2+1] + p0[cl+d2*2+1])));
                        dst[d2] = __floats2half2_rn(v0, v1);
                    }
                } else {
                    // seq logits: full dot32 owned by this thread
                    int lg = l0 + l;
                    const float* sq = &g_swq[lg*HDM + cl];
                    float pv = g_lbias[lg*NH + h];
                    #pragma unroll
                    for(int d=0; d<32; d++) pv += sq[d]*srow[d];
                    g_logit[(lg*NH + h)*NS + n] = pv;
                }
            }
        }
    } else {  // MODE 2: gate + pack into a_pk
        for(int seg = tid; seg < 512; seg += 128){
            int q = seg>>2, ss = seg&3;
            int s = nt*4 + ss;
            size_t rr = (size_t)s*LR + mt*128 + q;
            const __half2* gr = (const __half2*)&g_gate[rr*HDM + z*DHH];
            const float* srow = &st[q*129 + ss*32];
            __half2* dst = (__half2*)&a_pk[rr*256 + z*DHH];
            #pragma unroll
            for(int d2=0; d2<16; d2++){
                float2 g2 = __half22float2(gr[d2]);
                dst[d2] = __floats2half2_rn(srow[d2*2]*g2.x, srow[d2*2+1]*g2.y);
            }
        }
    }
}

// ---------------- 5. softmax over n + scale q_pk in place ----------------
__global__ void seq_softmax_kernel(){
    __shared__ float sh[8];
    __shared__ float wsh[NS];
    int l = blockIdx.x >> 3, h = blockIdx.x & 7;
    int tid = threadIdx.x;
    float x = g_logit[(l*NH+h)*NS + tid];
    float m = warpMax(x);
    if((tid&31)==0) sh[tid>>5]=m;
    __syncthreads();
    if(tid<32){ float mm=(tid<8)?sh[tid]:-1e30f; mm=warpMax(mm); if(tid==0) sh[0]=mm; }
    __syncthreads();
    m = sh[0];
    __syncthreads();
    float e = expf(x - m);
    float s = warpRed(e);
    if((tid&31)==0) sh[tid>>5]=s;
    __syncthreads();
    if(tid<32){ float ss=(tid<8)?sh[tid]:0.f; ss=warpRed(ss); if(tid==0) sh[0]=ss; }
    __syncthreads();
    s = sh[0];
    wsh[tid] = e / s;
    __syncthreads();
    __half2* qp = (__half2*)(q_pk + (size_t)(h*LR + l)*8192);
    for(int i=tid; i<4096; i+=256){
        float w = wsh[i>>4];
        float2 v = __half22float2(qp[i]);
        qp[i] = __floats2half2_rn(v.x*w, v.y*w);
    }
}

// ---------------- 6. pair bias = LN(pair) @ wb -> written directly into g_attn ----------------
__global__ void bias_kernel(const float* __restrict__ pair, const float* __restrict__ g,
                            const float* __restrict__ b, const float* __restrict__ wb){
    __shared__ float wbs[NH][DP];
    int tid = threadIdx.x;
    for(int idx=tid; idx<NH*DP; idx+=256){
        int h = idx / DP, k = idx % DP;
        wbs[h][k] = wb[k*NH + h];
    }
    __syncthreads();
    int warp = tid >> 5, lane = tid & 31;
    int p = blockIdx.x*8 + warp;
    float4 xv = ((const float4*)(pair + (size_t)p*DP))[lane];
    float sum = xv.x+xv.y+xv.z+xv.w;
    float sq  = xv.x*xv.x+xv.y*xv.y+xv.z*xv.z+xv.w*xv.w;
    sum = warpRed(sum); sq = warpRed(sq);
    float mean = sum*(1.f/DP);
    float var  = sq*(1.f/DP) - mean*mean;
    float inv  = rsqrtf(var + 1e-5f);
    float4 gv = ((const float4*)g)[lane];
    float4 bv = ((const float4*)b)[lane];
    float xn0 = (xv.x-mean)*inv*gv.x + bv.x;
    float xn1 = (xv.y-mean)*inv*gv.y + bv.y;
    float xn2 = (xv.z-mean)*inv*gv.z + bv.z;
    float xn3 = (xv.w-mean)*inv*gv.w + bv.w;
    #pragma unroll
    for(int h=0;h<NH;h++){
        float4 wv4 = ((const float4*)(wbs[h]))[lane];
        float prt = xn0*wv4.x + xn1*wv4.y + xn2*wv4.z + xn3*wv4.w;
        prt = warpRed(prt);
        if(lane==0) g_attn[h*LL + p] = prt;     // seed logits with bias
    }
}

// ---------------- 8. softmax over k -> p_pk fp16 ----------------
__global__ void attn_softmax_kernel(){
    __shared__ float sh[4];
    int row = blockIdx.x;   // h*LR + q
    const float* a = g_attn + (size_t)row*LR;
    int tid = threadIdx.x;  // 128 threads
    float x0 = a[tid];
    float x1 = a[tid+128];
    float x2 = a[tid+256];
    float m = fmaxf(x0, fmaxf(x1, x2));
    m = warpMax(m);
    if((tid&31)==0) sh[tid>>5]=m;
    __syncthreads();
    if(tid<32){ float mm=(tid<4)?sh[tid]:-1e30f; mm=warpMax(mm); if(tid==0) sh[0]=mm; }
    __syncthreads();
    m = sh[0];
    __syncthreads();
    x0 = expf(x0-m); x1 = expf(x1-m); x2 = expf(x2-m);
    float s = warpRed(x0+x1+x2);
    if((tid&31)==0) sh[tid>>5]=s;
    __syncthreads();
    if(tid<32){ float ss=(tid<4)?sh[tid]:0.f; ss=warpRed(ss); if(tid==0) sh[0]=ss; }
    __syncthreads();
    s = sh[0];
    float rcp = 1.f/s;
    __half* pp = p_pk + (size_t)row*384;
    pp[tid]     = __float2half(x0*rcp);
    pp[tid+128] = __float2half(x1*rcp);
    pp[tid+256] = __float2half(x2*rcp);
}

// ---------------- launch ----------------
extern "C" void kernel_launch(void* const* d_in, const int* in_sizes, int n_in,
                              void* d_out, int out_size){
    const float* msa       = (const float*)d_in[0];
    const float* pair      = (const float*)d_in[1];
    const float* ln_msa_g  = (const float*)d_in[2];
    const float* ln_msa_b  = (const float*)d_in[3];
    const float* ln_pair_g = (const float*)d_in[4];
    const float* ln_pair_b = (const float*)d_in[5];
    const float* sw_q_w    = (const float*)d_in[6];
    const float* sw_q_b    = (const float*)d_in[7];
    const float* sw_k_w    = (const float*)d_in[8];
    const float* sw_k_b    = (const float*)d_in[9];
    const float* wq        = (const float*)d_in[10];
    const float* wk        = (const float*)d_in[11];
    const float* wv        = (const float*)d_in[12];
    const float* wb        = (const float*)d_in[13];
    const float* wg        = (const float*)d_in[14];
    const float* bg        = (const float*)d_in[15];
    const float* wo        = (const float*)d_in[16];
    const float* bo        = (const float*)d_in[17];
    float* out = (float*)d_out;

    cudaFuncSetAttribute(gemm_mma<0>, cudaFuncAttributeMaxDynamicSharedMemorySize, GSMEM_BYTES);
    cudaFuncSetAttribute(gemm_mma<1>, cudaFuncAttributeMaxDynamicSharedMemorySize, GSMEM_BYTES);
    cudaFuncSetAttribute(gemm_mma<2>, cudaFuncAttributeMaxDynamicSharedMemorySize, GSMEM_BYTES);
    cudaFuncSetAttribute(gemm_mma<3>, cudaFuncAttributeMaxDynamicSharedMemorySize, GSMEM_BYTES);

    ln_msa_kernel<<<NL, 256>>>(msa, ln_msa_g, ln_msa_b);
    pack_w_kernel<<<1536, 256>>>(wq, wk, wv, wg, sw_k_w, wo);
    swq_kernel<<<LR, 256>>>(sw_q_w, sw_q_b, sw_k_b);
    bias_kernel<<<LL/8, 256>>>(pair, ln_pair_g, ln_pair_b, wb);   // seeds g_attn

    // proj: [98304 x 1280], K=256
    gemm_mma<0><<<dim3(10, 768, 1), 128, GSMEM_BYTES>>>(bg, nullptr);

    seq_softmax_kernel<<<LR*NH, 256>>>();

    // qk: per head [384 x 384], K=8192, split-K x4 -> atomicAdd onto bias
    gemm_mma<1><<<dim3(3, 3, NH*4), 128, GSMEM_BYTES>>>(nullptr, nullptr);

    attn_softmax_kernel<<<NH*LR, 128>>>();

    // av: per head [384 x 8192], K=384
    gemm_mma<2><<<dim3(64, 3, NH), 128, GSMEM_BYTES>>>(nullptr, nullptr);

    // out: [98304 x 256], K=256
    gemm_mma<3><<<dim3(2, 768, 1), 128, GSMEM_BYTES>>>(bo, out);
}